// round 10
// baseline (speedup 1.0000x reference)
#include <cuda_runtime.h>
#include <cuda_bf16.h>
#include <math.h>
#include <stdint.h>

#define VOCABN 50000
#define EMBN   300
#define KPAD   320     // EMB padded to 10 chunks of 32
#define TLEN   256
#define HIDN   512
#define G4     2048    // 4*HID
#define NCLSN  10
#define BATCHN 64
#define MROWS  (TLEN*BATCHN)

// ---------------------------------------------------------------------------
// Device scratch
// ---------------------------------------------------------------------------
__device__ __align__(256) float g_xz[2][TLEN][BATCHN][G4]; // permuted gate cols
__device__ __align__(256) float g_h[2][2][BATCHN][HIDN];   // fp32 h (final step, for dense)
__device__ unsigned g_bar;                                 // grid barrier counter

__device__ __align__(256) __nv_bfloat16 g_Ahi[(size_t)MROWS * KPAD];
__device__ __align__(256) __nv_bfloat16 g_Alo[(size_t)MROWS * KPAD];
__device__ __align__(256) __nv_bfloat16 g_Bhi[(size_t)2 * G4 * KPAD];
__device__ __align__(256) __nv_bfloat16 g_Blo[(size_t)2 * G4 * KPAD];
__device__ __align__(256) float g_biasp[2 * G4];

// recurrence operands: h as bf16 hi/lo planes, Wh^T (permuted) as bf16 hi/lo
__device__ __align__(256) __nv_bfloat16 g_hb[2][2][2][BATCHN][HIDN];   // [dir][pp][plane][b][k]
__device__ __align__(256) __nv_bfloat16 g_WhT[2][2][G4][HIDN];         // [dir][plane][p][k]

__device__ __forceinline__ int perm_src(int p) {
    return ((p >> 3) & 3) * HIDN + (p >> 5) * 8 + (p & 7);
}

__device__ __forceinline__ uint32_t smem_to_u32(const void* p) {
    uint32_t a;
    asm("{ .reg .u64 t; cvta.to.shared.u64 t, %1; cvt.u32.u64 %0, t; }"
        : "=r"(a) : "l"(p));
    return a;
}

// ---------------------------------------------------------------------------
// mma.sync / ldmatrix / cp.async helpers (baseline PTX, no 'a' features)
// ---------------------------------------------------------------------------
#define LDSM_X4(r0, r1, r2, r3, addr) \
    asm volatile("ldmatrix.sync.aligned.m8n8.x4.shared.b16 {%0,%1,%2,%3}, [%4];" \
        : "=r"(r0), "=r"(r1), "=r"(r2), "=r"(r3) : "r"(addr))

#define MMA_BF16(c, a, b) \
    asm volatile("mma.sync.aligned.m16n8k16.row.col.f32.bf16.bf16.f32 " \
        "{%0,%1,%2,%3}, {%4,%5,%6,%7}, {%8,%9}, {%0,%1,%2,%3};" \
        : "+f"((c)[0]), "+f"((c)[1]), "+f"((c)[2]), "+f"((c)[3]) \
        : "r"((a)[0]), "r"((a)[1]), "r"((a)[2]), "r"((a)[3]), \
          "r"((b)[0]), "r"((b)[1]))

#define CP_ASYNC16(dst, src) \
    asm volatile("cp.async.cg.shared.global [%0], [%1], 16;" \
        :: "r"(dst), "l"(src) : "memory")
#define CP_COMMIT() asm volatile("cp.async.commit_group;" ::: "memory")
#define CP_WAIT2()  asm volatile("cp.async.wait_group 2;" ::: "memory")
#define CP_WAIT1()  asm volatile("cp.async.wait_group 1;" ::: "memory")
#define CP_WAIT0()  asm volatile("cp.async.wait_group 0;" ::: "memory")

// swizzle of a 16B-chunk index within a 1KB row (XOR low 3 bits with row&7)
__device__ __forceinline__ uint32_t swz16(uint32_t c16, uint32_t row) {
    return (c16 & ~7u) | ((c16 ^ row) & 7u);
}

__device__ __forceinline__ float fsig(float x) {
    return __fdividef(1.f, 1.f + __expf(-x));
}

// ---------------------------------------------------------------------------
// Prep kernels
// ---------------------------------------------------------------------------
__global__ __launch_bounds__(KPAD) void prep_w(
    const float* __restrict__ Wx_f, const float* __restrict__ b_f,
    const float* __restrict__ Wx_b, const float* __restrict__ b_b)
{
    int n = blockIdx.x, dir = blockIdx.y, k = threadIdx.x;
    if (n == 0 && dir == 0 && k == 0) g_bar = 0u;     // grid-barrier reset
    int src = perm_src(n);
    const float* Wx = dir ? Wx_b : Wx_f;
    float v = (k < EMBN) ? Wx[(size_t)k * G4 + src] : 0.f;
    __nv_bfloat16 hi = __float2bfloat16(v);
    __nv_bfloat16 lo = __float2bfloat16(v - __bfloat162float(hi));
    size_t idx = (size_t)(dir * G4 + n) * KPAD + k;
    g_Bhi[idx] = hi;
    g_Blo[idx] = lo;
    if (k == 0) g_biasp[dir * G4 + n] = (dir ? b_b : b_f)[src];
}

__global__ __launch_bounds__(KPAD) void prep_a(
    const int* __restrict__ x, const float* __restrict__ emb)
{
    int row = blockIdx.x;
    int t = row >> 6, b = row & 63;
    __shared__ int tok;
    if (threadIdx.x == 0) tok = x[b * TLEN + t];
    __syncthreads();
    int k = threadIdx.x;
    float v = (k < EMBN) ? emb[(size_t)tok * EMBN + k] : 0.f;
    __nv_bfloat16 hi = __float2bfloat16(v);
    __nv_bfloat16 lo = __float2bfloat16(v - __bfloat162float(hi));
    size_t idx = (size_t)row * KPAD + k;
    g_Ahi[idx] = hi;
    g_Alo[idx] = lo;
}

// Wh^T with gate-column permutation, bf16 hi/lo planes, k-contiguous rows
__global__ __launch_bounds__(HIDN) void prep_wh(
    const float* __restrict__ Wh_f, const float* __restrict__ Wh_b)
{
    int p = blockIdx.x, dir = blockIdx.y, k = threadIdx.x;
    int src = perm_src(p);
    float v = (dir ? Wh_b : Wh_f)[(size_t)k * G4 + src];
    __nv_bfloat16 hi = __float2bfloat16(v);
    __nv_bfloat16 lo = __float2bfloat16(v - __bfloat162float(hi));
    g_WhT[dir][0][p][k] = hi;
    g_WhT[dir][1][p][k] = lo;
}

// ---------------------------------------------------------------------------
// Tensor-core (mma.sync bf16x3) input projection.
// NEW vs R9: 3-stage cp.async pipeline (keeps 2 chunks in flight, hides the
// per-chunk L2 round trip that capped tensor at 71%). 96KB/CTA x 2 CTAs/SM.
// ---------------------------------------------------------------------------
#define GT_STAGE 32768
#define GT_SMEM  (3 * GT_STAGE)
#define NCHUNK   10

__global__ __launch_bounds__(256, 2) void gemm_mma()
{
    extern __shared__ char sm[];
    const uint32_t smb = smem_to_u32(sm);
    const int tid = threadIdx.x, wid = tid >> 5, lane = tid & 31;

    const int ntile = blockIdx.x & 15;
    const int mtile = (blockIdx.x >> 4) & 127;
    const int dir   = blockIdx.x >> 11;
    const int m0 = mtile * 128, n0 = ntile * 128;

    const int mwarp = (wid >> 2) * 64;
    const int nwarp = (wid & 3) * 32;

    const int crow = tid >> 3;
    const int cc   = tid & 7;
    const __nv_bfloat16* srcA_base = (cc < 4) ? g_Ahi : g_Alo;
    const __nv_bfloat16* srcB_base = (cc < 4) ? g_Bhi : g_Blo;
    const int ksub = (cc & 3) * 8;

    const int a_row = (lane & 7) + ((lane >> 3) & 1) * 8;
    const int a_cad = (lane >> 4) & 1;
    const int b_row = (lane & 7) + ((lane >> 4) & 1) * 8;
    const int b_cad = (lane >> 3) & 1;

    float c[4][4][4];
    #pragma unroll
    for (int i = 0; i < 4; i++)
        #pragma unroll
        for (int j = 0; j < 4; j++)
            #pragma unroll
            for (int e = 0; e < 4; e++) c[i][j][e] = 0.f;

    #define ISSUE_COPY(kc, stage) do {                                         \
        uint32_t sA = smb + (stage) * GT_STAGE;                                \
        uint32_t sB = sA + 16384;                                              \
        _Pragma("unroll")                                                      \
        for (int q = 0; q < 4; q++) {                                          \
            int row = crow + q * 32;                                           \
            uint32_t dof = (uint32_t)row * 128 + ((cc ^ (row & 7)) * 16);      \
            const __nv_bfloat16* sa = srcA_base +                              \
                (size_t)(m0 + row) * KPAD + (kc) * 32 + ksub;                  \
            const __nv_bfloat16* sb = srcB_base +                              \
                (size_t)(dir * G4 + n0 + row) * KPAD + (kc) * 32 + ksub;       \
            CP_ASYNC16(sA + dof, sa);                                          \
            CP_ASYNC16(sB + dof, sb);                                          \
        }                                                                      \
        CP_COMMIT();                                                           \
    } while (0)

    ISSUE_COPY(0, 0);
    ISSUE_COPY(1, 1);

    #pragma unroll 1
    for (int kc = 0; kc < NCHUNK; kc++) {
        if (kc + 2 < NCHUNK) {
            ISSUE_COPY(kc + 2, (kc + 2) % 3);
            CP_WAIT2();
        } else if (kc + 1 < NCHUNK) {
            CP_WAIT1();
        } else {
            CP_WAIT0();
        }
        __syncthreads();

        const uint32_t sA = smb + (kc % 3) * GT_STAGE;
        const uint32_t sB = sA + 16384;

        #pragma unroll
        for (int ks = 0; ks < 2; ks++) {
            uint32_t ah[4][4], al[4][4], bh[4][2], bl[4][2];
            #pragma unroll
            for (int mt = 0; mt < 4; mt++) {
                int row = mwarp + mt * 16 + a_row;
                int swzr = row & 7;
                uint32_t oh = sA + (uint32_t)row * 128 +
                              (((ks * 2 + a_cad)     ^ swzr) * 16);
                uint32_t ol = sA + (uint32_t)row * 128 +
                              (((4 + ks * 2 + a_cad) ^ swzr) * 16);
                LDSM_X4(ah[mt][0], ah[mt][1], ah[mt][2], ah[mt][3], oh);
                LDSM_X4(al[mt][0], al[mt][1], al[mt][2], al[mt][3], ol);
            }
            #pragma unroll
            for (int j = 0; j < 2; j++) {
                int row = nwarp + j * 16 + b_row;
                int swzr = row & 7;
                uint32_t oh = sB + (uint32_t)row * 128 +
                              (((ks * 2 + b_cad)     ^ swzr) * 16);
                uint32_t ol = sB + (uint32_t)row * 128 +
                              (((4 + ks * 2 + b_cad) ^ swzr) * 16);
                LDSM_X4(bh[2*j][0], bh[2*j][1], bh[2*j+1][0], bh[2*j+1][1], oh);
                LDSM_X4(bl[2*j][0], bl[2*j][1], bl[2*j+1][0], bl[2*j+1][1], ol);
            }
            #pragma unroll
            for (int mt = 0; mt < 4; mt++)
                #pragma unroll
                for (int nt = 0; nt < 4; nt++) {
                    MMA_BF16(c[mt][nt], ah[mt], bh[nt]);
                    MMA_BF16(c[mt][nt], ah[mt], bl[nt]);
                    MMA_BF16(c[mt][nt], al[mt], bh[nt]);
                }
        }
        __syncthreads();
    }

    const int qrow = lane >> 2;
    const int qcol = (lane & 3) * 2;
    #pragma unroll
    for (int nt = 0; nt < 4; nt++) {
        int coll = nwarp + nt * 8 + qcol;
        int col  = n0 + coll;
        float2 bv = *(const float2*)&g_biasp[dir * G4 + col];
        #pragma unroll
        for (int mt = 0; mt < 4; mt++) {
            #pragma unroll
            for (int half = 0; half < 2; half++) {
                int g = m0 + mwarp + mt * 16 + qrow + half * 8;
                int t = g >> 6, b = g & 63;
                int tout = dir ? (TLEN - 1 - t) : t;
                float2 v;
                v.x = c[mt][nt][half * 2 + 0] + bv.x;
                v.y = c[mt][nt][half * 2 + 1] + bv.y;
                *(float2*)&g_xz[dir][tout][b][col] = v;
            }
        }
    }
}

// ---------------------------------------------------------------------------
// Kernel 2: persistent bidirectional LSTM recurrence, mma.sync bf16x3.
// 8 warps = 2(M:32 rows) x 4(K:128). Same structure as R9 (verified 1657us).
// NEW: gate stage remapped to (b, adjacent-rr-pair) per thread:
//   float2 spill reads (half the LDS), packed bf162 h stores (half the STGs),
//   float2 final g_h store. Cell state stays register-fixed (2 units/thread).
// ---------------------------------------------------------------------------
#define LS_A     0                   // A planes: 2 x 64KB (rows b, 1KB each)
#define LS_B     131072              // B planes: 2 x 32KB (rows n, 1KB each)
#define LS_SPILL 196608              // 4 bufs x [64][34] fp32 = 4 x 8704
#define LSTM_SMEM_BYTES (196608 + 4 * 8704)   // 231424

__global__ __launch_bounds__(256, 1) void lstm_kernel()
{
    extern __shared__ char sm[];
    const uint32_t smb = smem_to_u32(sm);
    float* spill = (float*)(sm + LS_SPILL);

    const int tid   = threadIdx.x;
    const int wid   = tid >> 5, lane = tid & 31;
    const int dir   = blockIdx.x >> 6;
    const int slice = blockIdx.x & 63;

    const int mhalf = wid & 1;        // M half: rows mhalf*32..+31
    const int kq    = wid >> 1;       // K quarter: k kq*128..+127

    // ---- one-time: load Wh^T slice (hi/lo) into smem ----
    #pragma unroll
    for (int i = tid; i < 4096; i += 256) {       // 4096 16B chunks
        int plane = i >> 11;
        int row   = (i >> 6) & 31;
        int c16   = i & 63;
        const __nv_bfloat16* src = &g_WhT[dir][plane][slice * 32 + row][c16 * 8];
        uint32_t dst = smb + LS_B + plane * 32768 + row * 1024 + swz16(c16, row) * 16;
        CP_ASYNC16(dst, src);
    }
    CP_COMMIT();
    CP_WAIT0();
    __syncthreads();

    // ldmatrix lane geometry (verified)
    const int a_row = (lane & 7) + ((lane >> 3) & 1) * 8;
    const int a_cad = (lane >> 4) & 1;
    const int b_row = (lane & 7) + ((lane >> 4) & 1) * 8;
    const int b_cad = (lane >> 3) & 1;
    const int qrow  = lane >> 2;
    const int qcol  = (lane & 3) * 2;
    const unsigned nb = gridDim.x;

    // gate-stage mapping: thread -> (gb, grp) covering units grp, grp+1
    const int gb  = tid >> 2;
    const int grp = (tid & 3) * 2;
    float cell[2] = {0.f, 0.f};       // register cell state for the 2 units

    for (int s = 0; s < TLEN; s++) {
        // ---- stage this warp's A slice: hi plane group, then lo plane ----
        if (s > 0) {
            const __nv_bfloat16* hb = &g_hb[dir][s & 1][0][0][0];
            #pragma unroll
            for (int q = 0; q < 16; q++) {        // plane 0 (hi)
                int i = lane + q * 32;
                int rloc  = (i >> 4) & 31;
                int ccc   = i & 15;
                int row   = mhalf * 32 + rloc;
                int gc16  = kq * 16 + ccc;
                const __nv_bfloat16* src = hb + (size_t)row * HIDN + gc16 * 8;
                uint32_t dst = smb + LS_A + row * 1024 + swz16(gc16, row) * 16;
                CP_ASYNC16(dst, src);
            }
            CP_COMMIT();
            #pragma unroll
            for (int q = 0; q < 16; q++) {        // plane 1 (lo)
                int i = lane + q * 32;
                int rloc  = (i >> 4) & 31;
                int ccc   = i & 15;
                int row   = mhalf * 32 + rloc;
                int gc16  = kq * 16 + ccc;
                const __nv_bfloat16* src = hb + (size_t)(BATCHN * HIDN)
                                             + (size_t)row * HIDN + gc16 * 8;
                uint32_t dst = smb + LS_A + 65536 + row * 1024 +
                               swz16(gc16, row) * 16;
                CP_ASYNC16(dst, src);
            }
            CP_COMMIT();
        }

        // ---- init accumulators from precomputed input projection ----
        float c[2][4][4];
        if (kq == 0) {
            #pragma unroll
            for (int mt = 0; mt < 2; mt++)
                #pragma unroll
                for (int half = 0; half < 2; half++) {
                    int b = mhalf * 32 + mt * 16 + qrow + half * 8;
                    const float* xzp = &g_xz[dir][s][b][slice * 32];
                    #pragma unroll
                    for (int nt = 0; nt < 4; nt++) {
                        float2 v = *(const float2*)&xzp[nt * 8 + qcol];
                        c[mt][nt][half * 2 + 0] = v.x;
                        c[mt][nt][half * 2 + 1] = v.y;
                    }
                }
        } else {
            #pragma unroll
            for (int mt = 0; mt < 2; mt++)
                #pragma unroll
                for (int nt = 0; nt < 4; nt++)
                    #pragma unroll
                    for (int e = 0; e < 4; e++) c[mt][nt][e] = 0.f;
        }

        // ---- MMA: phase A (hi plane) under WAIT1, phase B after WAIT0 ----
        if (s > 0) {
            CP_WAIT1();
            #pragma unroll 2
            for (int j = 0; j < 8; j++) {
                int gc = kq * 16 + j * 2;
                uint32_t ah[2][4], bh[4][2], bl[4][2];
                #pragma unroll
                for (int mt = 0; mt < 2; mt++) {
                    int row = mhalf * 32 + mt * 16 + a_row;
                    uint32_t oh = smb + LS_A + row * 1024 + swz16(gc + a_cad, row) * 16;
                    LDSM_X4(ah[mt][0], ah[mt][1], ah[mt][2], ah[mt][3], oh);
                }
                #pragma unroll
                for (int jn = 0; jn < 2; jn++) {
                    int row = jn * 16 + b_row;
                    uint32_t oh = smb + LS_B + row * 1024 + swz16(gc + b_cad, row) * 16;
                    LDSM_X4(bh[2*jn][0], bh[2*jn][1], bh[2*jn+1][0], bh[2*jn+1][1], oh);
                    LDSM_X4(bl[2*jn][0], bl[2*jn][1], bl[2*jn+1][0], bl[2*jn+1][1],
                            oh + 32768);
                }
                #pragma unroll
                for (int mt = 0; mt < 2; mt++)
                    #pragma unroll
                    for (int nt = 0; nt < 4; nt++) {
                        MMA_BF16(c[mt][nt], ah[mt], bh[nt]);
                        MMA_BF16(c[mt][nt], ah[mt], bl[nt]);
                    }
            }
            CP_WAIT0();
            #pragma unroll 2
            for (int j = 0; j < 8; j++) {
                int gc = kq * 16 + j * 2;
                uint32_t al[2][4], bh[4][2];
                #pragma unroll
                for (int mt = 0; mt < 2; mt++) {
                    int row = mhalf * 32 + mt * 16 + a_row;
                    uint32_t ol = smb + LS_A + 65536 + row * 1024 +
                                  swz16(gc + a_cad, row) * 16;
                    LDSM_X4(al[mt][0], al[mt][1], al[mt][2], al[mt][3], ol);
                }
                #pragma unroll
                for (int jn = 0; jn < 2; jn++) {
                    int row = jn * 16 + b_row;
                    uint32_t oh = smb + LS_B + row * 1024 + swz16(gc + b_cad, row) * 16;
                    LDSM_X4(bh[2*jn][0], bh[2*jn][1], bh[2*jn+1][0], bh[2*jn+1][1], oh);
                }
                #pragma unroll
                for (int mt = 0; mt < 2; mt++)
                    #pragma unroll
                    for (int nt = 0; nt < 4; nt++)
                        MMA_BF16(c[mt][nt], al[mt], bh[nt]);
            }
        }

        // ---- single-round: every warp stores partials to its kq buffer ----
        __syncthreads();
        {
            float* bp = spill + kq * 2176;   // [64][34]
            #pragma unroll
            for (int mt = 0; mt < 2; mt++)
                #pragma unroll
                for (int half = 0; half < 2; half++) {
                    int r = mhalf * 32 + mt * 16 + qrow + half * 8;
                    #pragma unroll
                    for (int nt = 0; nt < 4; nt++) {
                        float2 v;
                        v.x = c[mt][nt][half * 2 + 0];
                        v.y = c[mt][nt][half * 2 + 1];
                        *(float2*)&bp[r * 34 + nt * 8 + qcol] = v;
                    }
                }
        }
        __syncthreads();

        // ---- gates: 256 threads x 2 adjacent units, float2 reads ----
        {
            float2 z2[4];
            #pragma unroll
            for (int g = 0; g < 4; g++) {
                int off = gb * 34 + g * 8 + grp;
                float2 a0 = *(const float2*)&spill[off];
                float2 a1 = *(const float2*)&spill[2176 + off];
                float2 a2 = *(const float2*)&spill[4352 + off];
                float2 a3 = *(const float2*)&spill[6528 + off];
                z2[g].x = (a0.x + a1.x) + (a2.x + a3.x);
                z2[g].y = (a0.y + a1.y) + (a2.y + a3.y);
            }
            float hh[2];
            #pragma unroll
            for (int u = 0; u < 2; u++) {
                float zi = u ? z2[0].y : z2[0].x;
                float zf = u ? z2[1].y : z2[1].x;
                float zg = u ? z2[2].y : z2[2].x;
                float zo = u ? z2[3].y : z2[3].x;
                float gi = fsig(zi);
                float gf = fsig(zf);
                float gg = fmaxf(zg, 0.f);
                float go = fsig(zo);
                float cv = gf * cell[u] + gi * gg;
                cell[u] = cv;
                hh[u] = go * fmaxf(cv, 0.f);
            }
            __nv_bfloat162 vhi, vlo;
            vhi.x = __float2bfloat16(hh[0]);
            vhi.y = __float2bfloat16(hh[1]);
            vlo.x = __float2bfloat16(hh[0] - __bfloat162float(vhi.x));
            vlo.y = __float2bfloat16(hh[1] - __bfloat162float(vhi.y));
            int kk = slice * 8 + grp;
            int pp = (s + 1) & 1;
            *(__nv_bfloat162*)&g_hb[dir][pp][0][gb][kk] = vhi;
            *(__nv_bfloat162*)&g_hb[dir][pp][1][gb][kk] = vlo;
            if (s == TLEN - 1) {
                float2 vf; vf.x = hh[0]; vf.y = hh[1];
                *(float2*)&g_h[dir][0][gb][kk] = vf;
            }
        }

        if (s < TLEN - 1) {
            // release/acquire grid barrier (no L1-flushing threadfence)
            __syncthreads();
            if (tid == 0) {
                asm volatile("red.release.gpu.global.add.u32 [%0], %1;"
                             :: "l"(&g_bar), "r"(1u) : "memory");
                unsigned target = (unsigned)(s + 1) * nb;
                unsigned v;
                do {
                    asm volatile("ld.acquire.gpu.global.u32 %0, [%1];"
                                 : "=r"(v) : "l"(&g_bar) : "memory");
                } while (v < target);
            }
            __syncthreads();
        }
    }
}

// ---------------------------------------------------------------------------
// Kernel 3: dense + softmax
// ---------------------------------------------------------------------------
__global__ __launch_bounds__(320) void dense_kernel(
    const float* __restrict__ Wd, const float* __restrict__ bd,
    float* __restrict__ out)
{
    const int b = blockIdx.x;
    const int w = threadIdx.x >> 5, lane = threadIdx.x & 31;
    __shared__ float logits[NCLSN];

    float sum = 0.f;
    for (int k = lane; k < 2 * HIDN; k += 32) {
        float hv = (k < HIDN) ? g_h[0][0][b][k] : g_h[1][0][b][k - HIDN];
        sum = fmaf(hv, Wd[k * NCLSN + w], sum);
    }
    #pragma unroll
    for (int off = 16; off > 0; off >>= 1)
        sum += __shfl_down_sync(0xffffffffu, sum, off);
    if (lane == 0) logits[w] = sum + bd[w];
    __syncthreads();

    if (threadIdx.x == 0) {
        float mx = logits[0];
        #pragma unroll
        for (int n = 1; n < NCLSN; n++) mx = fmaxf(mx, logits[n]);
        float es[NCLSN], ssum = 0.f;
        #pragma unroll
        for (int n = 0; n < NCLSN; n++) { es[n] = expf(logits[n] - mx); ssum += es[n]; }
        float inv = 1.f / ssum;
        #pragma unroll
        for (int n = 0; n < NCLSN; n++) out[b * NCLSN + n] = es[n] * inv;
    }
}

// ---------------------------------------------------------------------------
extern "C" void kernel_launch(void* const* d_in, const int* in_sizes, int n_in,
                              void* d_out, int out_size)
{
    const int*   x    = (const int*)  d_in[0];
    const float* emb  = (const float*)d_in[1];
    const float* Wx_f = (const float*)d_in[2];
    const float* Wh_f = (const float*)d_in[3];
    const float* b_f  = (const float*)d_in[4];
    const float* Wx_b = (const float*)d_in[5];
    const float* Wh_b = (const float*)d_in[6];
    const float* b_b  = (const float*)d_in[7];
    const float* Wd   = (const float*)d_in[8];
    const float* bd   = (const float*)d_in[9];
    float* out = (float*)d_out;

    (void)in_sizes; (void)n_in; (void)out_size;

    cudaFuncSetAttribute(gemm_mma,
                         cudaFuncAttributeMaxDynamicSharedMemorySize, GT_SMEM);
    cudaFuncSetAttribute(lstm_kernel,
                         cudaFuncAttributeMaxDynamicSharedMemorySize, LSTM_SMEM_BYTES);

    prep_w<<<dim3(G4, 2), KPAD>>>(Wx_f, b_f, Wx_b, b_b);
    prep_wh<<<dim3(G4, 2), HIDN>>>(Wh_f, Wh_b);
    prep_a<<<MROWS, KPAD>>>(x, emb);
    gemm_mma<<<2 * 128 * 16, 256, GT_SMEM>>>();
    lstm_kernel<<<128, 256, LSTM_SMEM_BYTES>>>();
    dense_kernel<<<BATCHN, 320>>>(Wd, bd, out);
}

// round 11
// speedup vs baseline: 1.0116x; 1.0116x over previous
#include <cuda_runtime.h>
#include <cuda_bf16.h>
#include <math.h>
#include <stdint.h>

#define VOCABN 50000
#define EMBN   300
#define KPAD   320     // EMB padded to 10 chunks of 32
#define TLEN   256
#define HIDN   512
#define G4     2048    // 4*HID
#define NCLSN  10
#define BATCHN 64
#define MROWS  (TLEN*BATCHN)

// ---------------------------------------------------------------------------
// Device scratch
// ---------------------------------------------------------------------------
__device__ __align__(256) float g_xz[2][TLEN][BATCHN][G4]; // permuted gate cols
__device__ __align__(256) float g_h[2][2][BATCHN][HIDN];   // fp32 h (final step, for dense)
__device__ unsigned g_bar;                                 // grid barrier counter

__device__ __align__(256) __nv_bfloat16 g_Ahi[(size_t)MROWS * KPAD];
__device__ __align__(256) __nv_bfloat16 g_Alo[(size_t)MROWS * KPAD];
__device__ __align__(256) __nv_bfloat16 g_Bhi[(size_t)2 * G4 * KPAD];
__device__ __align__(256) __nv_bfloat16 g_Blo[(size_t)2 * G4 * KPAD];
__device__ __align__(256) float g_biasp[2 * G4];

// recurrence operands: h as bf16 hi/lo planes, Wh^T (permuted) as bf16 hi/lo
__device__ __align__(256) __nv_bfloat16 g_hb[2][2][2][BATCHN][HIDN];   // [dir][pp][plane][b][k]
__device__ __align__(256) __nv_bfloat16 g_WhT[2][2][G4][HIDN];         // [dir][plane][p][k]

__device__ __forceinline__ int perm_src(int p) {
    return ((p >> 3) & 3) * HIDN + (p >> 5) * 8 + (p & 7);
}

__device__ __forceinline__ uint32_t smem_to_u32(const void* p) {
    uint32_t a;
    asm("{ .reg .u64 t; cvta.to.shared.u64 t, %1; cvt.u32.u64 %0, t; }"
        : "=r"(a) : "l"(p));
    return a;
}

// ---------------------------------------------------------------------------
// mma.sync / ldmatrix / cp.async helpers (baseline PTX, no 'a' features)
// ---------------------------------------------------------------------------
#define LDSM_X4(r0, r1, r2, r3, addr) \
    asm volatile("ldmatrix.sync.aligned.m8n8.x4.shared.b16 {%0,%1,%2,%3}, [%4];" \
        : "=r"(r0), "=r"(r1), "=r"(r2), "=r"(r3) : "r"(addr))

#define MMA_BF16(c, a, b) \
    asm volatile("mma.sync.aligned.m16n8k16.row.col.f32.bf16.bf16.f32 " \
        "{%0,%1,%2,%3}, {%4,%5,%6,%7}, {%8,%9}, {%0,%1,%2,%3};" \
        : "+f"((c)[0]), "+f"((c)[1]), "+f"((c)[2]), "+f"((c)[3]) \
        : "r"((a)[0]), "r"((a)[1]), "r"((a)[2]), "r"((a)[3]), \
          "r"((b)[0]), "r"((b)[1]))

#define CP_ASYNC16(dst, src) \
    asm volatile("cp.async.cg.shared.global [%0], [%1], 16;" \
        :: "r"(dst), "l"(src) : "memory")
#define CP_COMMIT() asm volatile("cp.async.commit_group;" ::: "memory")
#define CP_WAIT1()  asm volatile("cp.async.wait_group 1;" ::: "memory")
#define CP_WAIT0()  asm volatile("cp.async.wait_group 0;" ::: "memory")

// swizzle of a 16B-chunk index within a 1KB row (XOR low 3 bits with row&7)
__device__ __forceinline__ uint32_t swz16(uint32_t c16, uint32_t row) {
    return (c16 & ~7u) | ((c16 ^ row) & 7u);
}

__device__ __forceinline__ float fsig(float x) {
    return __fdividef(1.f, 1.f + __expf(-x));
}

// ---------------------------------------------------------------------------
// Prep kernels
// ---------------------------------------------------------------------------
__global__ __launch_bounds__(KPAD) void prep_w(
    const float* __restrict__ Wx_f, const float* __restrict__ b_f,
    const float* __restrict__ Wx_b, const float* __restrict__ b_b)
{
    int n = blockIdx.x, dir = blockIdx.y, k = threadIdx.x;
    if (n == 0 && dir == 0 && k == 0) g_bar = 0u;     // grid-barrier reset
    int src = perm_src(n);
    const float* Wx = dir ? Wx_b : Wx_f;
    float v = (k < EMBN) ? Wx[(size_t)k * G4 + src] : 0.f;
    __nv_bfloat16 hi = __float2bfloat16(v);
    __nv_bfloat16 lo = __float2bfloat16(v - __bfloat162float(hi));
    size_t idx = (size_t)(dir * G4 + n) * KPAD + k;
    g_Bhi[idx] = hi;
    g_Blo[idx] = lo;
    if (k == 0) g_biasp[dir * G4 + n] = (dir ? b_b : b_f)[src];
}

__global__ __launch_bounds__(KPAD) void prep_a(
    const int* __restrict__ x, const float* __restrict__ emb)
{
    int row = blockIdx.x;
    int t = row >> 6, b = row & 63;
    __shared__ int tok;
    if (threadIdx.x == 0) tok = x[b * TLEN + t];
    __syncthreads();
    int k = threadIdx.x;
    float v = (k < EMBN) ? emb[(size_t)tok * EMBN + k] : 0.f;
    __nv_bfloat16 hi = __float2bfloat16(v);
    __nv_bfloat16 lo = __float2bfloat16(v - __bfloat162float(hi));
    size_t idx = (size_t)row * KPAD + k;
    g_Ahi[idx] = hi;
    g_Alo[idx] = lo;
}

// Wh^T with gate-column permutation, bf16 hi/lo planes, k-contiguous rows
__global__ __launch_bounds__(HIDN) void prep_wh(
    const float* __restrict__ Wh_f, const float* __restrict__ Wh_b)
{
    int p = blockIdx.x, dir = blockIdx.y, k = threadIdx.x;
    int src = perm_src(p);
    float v = (dir ? Wh_b : Wh_f)[(size_t)k * G4 + src];
    __nv_bfloat16 hi = __float2bfloat16(v);
    __nv_bfloat16 lo = __float2bfloat16(v - __bfloat162float(hi));
    g_WhT[dir][0][p][k] = hi;
    g_WhT[dir][1][p][k] = lo;
}

// ---------------------------------------------------------------------------
// Tensor-core (mma.sync bf16x3) input projection — REVERTED to the verified
// 2-stage pipeline (298us, tensor 71%). 3-stage (R10) regressed: dynamic %3
// stage indexing + 192KB/SM smem shrank the L1 carveout.
// ---------------------------------------------------------------------------
#define GT_STAGE 32768
#define GT_SMEM  (2 * GT_STAGE)
#define NCHUNK   10

__global__ __launch_bounds__(256, 2) void gemm_mma()
{
    extern __shared__ char sm[];
    const uint32_t smb = smem_to_u32(sm);
    const int tid = threadIdx.x, wid = tid >> 5, lane = tid & 31;

    const int ntile = blockIdx.x & 15;
    const int mtile = (blockIdx.x >> 4) & 127;
    const int dir   = blockIdx.x >> 11;
    const int m0 = mtile * 128, n0 = ntile * 128;

    const int mwarp = (wid >> 2) * 64;
    const int nwarp = (wid & 3) * 32;

    const int crow = tid >> 3;
    const int cc   = tid & 7;
    const __nv_bfloat16* srcA_base = (cc < 4) ? g_Ahi : g_Alo;
    const __nv_bfloat16* srcB_base = (cc < 4) ? g_Bhi : g_Blo;
    const int ksub = (cc & 3) * 8;

    const int a_row = (lane & 7) + ((lane >> 3) & 1) * 8;
    const int a_cad = (lane >> 4) & 1;
    const int b_row = (lane & 7) + ((lane >> 4) & 1) * 8;
    const int b_cad = (lane >> 3) & 1;

    float c[4][4][4];
    #pragma unroll
    for (int i = 0; i < 4; i++)
        #pragma unroll
        for (int j = 0; j < 4; j++)
            #pragma unroll
            for (int e = 0; e < 4; e++) c[i][j][e] = 0.f;

    #define ISSUE_COPY(kc, stage) do {                                         \
        uint32_t sA = smb + (stage) * GT_STAGE;                                \
        uint32_t sB = sA + 16384;                                              \
        _Pragma("unroll")                                                      \
        for (int q = 0; q < 4; q++) {                                          \
            int row = crow + q * 32;                                           \
            uint32_t dof = (uint32_t)row * 128 + ((cc ^ (row & 7)) * 16);      \
            const __nv_bfloat16* sa = srcA_base +                              \
                (size_t)(m0 + row) * KPAD + (kc) * 32 + ksub;                  \
            const __nv_bfloat16* sb = srcB_base +                              \
                (size_t)(dir * G4 + n0 + row) * KPAD + (kc) * 32 + ksub;       \
            CP_ASYNC16(sA + dof, sa);                                          \
            CP_ASYNC16(sB + dof, sb);                                          \
        }                                                                      \
        CP_COMMIT();                                                           \
    } while (0)

    ISSUE_COPY(0, 0);

    #pragma unroll 1
    for (int kc = 0; kc < NCHUNK; kc++) {
        if (kc + 1 < NCHUNK) {
            ISSUE_COPY(kc + 1, (kc + 1) & 1);
            CP_WAIT1();
        } else {
            CP_WAIT0();
        }
        __syncthreads();

        const uint32_t sA = smb + (kc & 1) * GT_STAGE;
        const uint32_t sB = sA + 16384;

        #pragma unroll
        for (int ks = 0; ks < 2; ks++) {
            uint32_t ah[4][4], al[4][4], bh[4][2], bl[4][2];
            #pragma unroll
            for (int mt = 0; mt < 4; mt++) {
                int row = mwarp + mt * 16 + a_row;
                int swzr = row & 7;
                uint32_t oh = sA + (uint32_t)row * 128 +
                              (((ks * 2 + a_cad)     ^ swzr) * 16);
                uint32_t ol = sA + (uint32_t)row * 128 +
                              (((4 + ks * 2 + a_cad) ^ swzr) * 16);
                LDSM_X4(ah[mt][0], ah[mt][1], ah[mt][2], ah[mt][3], oh);
                LDSM_X4(al[mt][0], al[mt][1], al[mt][2], al[mt][3], ol);
            }
            #pragma unroll
            for (int j = 0; j < 2; j++) {
                int row = nwarp + j * 16 + b_row;
                int swzr = row & 7;
                uint32_t oh = sB + (uint32_t)row * 128 +
                              (((ks * 2 + b_cad)     ^ swzr) * 16);
                uint32_t ol = sB + (uint32_t)row * 128 +
                              (((4 + ks * 2 + b_cad) ^ swzr) * 16);
                LDSM_X4(bh[2*j][0], bh[2*j][1], bh[2*j+1][0], bh[2*j+1][1], oh);
                LDSM_X4(bl[2*j][0], bl[2*j][1], bl[2*j+1][0], bl[2*j+1][1], ol);
            }
            #pragma unroll
            for (int mt = 0; mt < 4; mt++)
                #pragma unroll
                for (int nt = 0; nt < 4; nt++) {
                    MMA_BF16(c[mt][nt], ah[mt], bh[nt]);
                    MMA_BF16(c[mt][nt], ah[mt], bl[nt]);
                    MMA_BF16(c[mt][nt], al[mt], bh[nt]);
                }
        }
        __syncthreads();
    }

    const int qrow = lane >> 2;
    const int qcol = (lane & 3) * 2;
    #pragma unroll
    for (int nt = 0; nt < 4; nt++) {
        int coll = nwarp + nt * 8 + qcol;
        int col  = n0 + coll;
        float2 bv = *(const float2*)&g_biasp[dir * G4 + col];
        #pragma unroll
        for (int mt = 0; mt < 4; mt++) {
            #pragma unroll
            for (int half = 0; half < 2; half++) {
                int g = m0 + mwarp + mt * 16 + qrow + half * 8;
                int t = g >> 6, b = g & 63;
                int tout = dir ? (TLEN - 1 - t) : t;
                float2 v;
                v.x = c[mt][nt][half * 2 + 0] + bv.x;
                v.y = c[mt][nt][half * 2 + 1] + bv.y;
                *(float2*)&g_xz[dir][tout][b][col] = v;
            }
        }
    }
}

// ---------------------------------------------------------------------------
// Kernel 2: persistent bidirectional LSTM recurrence, mma.sync bf16x3.
// R9 structure + R10 gate remap (both verified):
//  - plane-split staging (hi group / lo group, phase-A MMA under WAIT1)
//  - single-round 4-buffer K reduction (2 syncs)
//  - gate stage: thread -> (b, adjacent unit pair); float2 spill reads,
//    packed bf162 h stores, register cell state
//  - release/acquire grid barrier
// ---------------------------------------------------------------------------
#define LS_A     0                   // A planes: 2 x 64KB (rows b, 1KB each)
#define LS_B     131072              // B planes: 2 x 32KB (rows n, 1KB each)
#define LS_SPILL 196608              // 4 bufs x [64][34] fp32 = 4 x 8704
#define LSTM_SMEM_BYTES (196608 + 4 * 8704)   // 231424

__global__ __launch_bounds__(256, 1) void lstm_kernel()
{
    extern __shared__ char sm[];
    const uint32_t smb = smem_to_u32(sm);
    float* spill = (float*)(sm + LS_SPILL);

    const int tid   = threadIdx.x;
    const int wid   = tid >> 5, lane = tid & 31;
    const int dir   = blockIdx.x >> 6;
    const int slice = blockIdx.x & 63;

    const int mhalf = wid & 1;        // M half: rows mhalf*32..+31
    const int kq    = wid >> 1;       // K quarter: k kq*128..+127

    // ---- one-time: load Wh^T slice (hi/lo) into smem ----
    #pragma unroll
    for (int i = tid; i < 4096; i += 256) {       // 4096 16B chunks
        int plane = i >> 11;
        int row   = (i >> 6) & 31;
        int c16   = i & 63;
        const __nv_bfloat16* src = &g_WhT[dir][plane][slice * 32 + row][c16 * 8];
        uint32_t dst = smb + LS_B + plane * 32768 + row * 1024 + swz16(c16, row) * 16;
        CP_ASYNC16(dst, src);
    }
    CP_COMMIT();
    CP_WAIT0();
    __syncthreads();

    // ldmatrix lane geometry (verified)
    const int a_row = (lane & 7) + ((lane >> 3) & 1) * 8;
    const int a_cad = (lane >> 4) & 1;
    const int b_row = (lane & 7) + ((lane >> 4) & 1) * 8;
    const int b_cad = (lane >> 3) & 1;
    const int qrow  = lane >> 2;
    const int qcol  = (lane & 3) * 2;
    const unsigned nb = gridDim.x;

    // gate-stage mapping: thread -> (gb, grp) covering units grp, grp+1
    const int gb  = tid >> 2;
    const int grp = (tid & 3) * 2;
    float cell[2] = {0.f, 0.f};       // register cell state for the 2 units

    for (int s = 0; s < TLEN; s++) {
        // ---- stage this warp's A slice: hi plane group, then lo plane ----
        if (s > 0) {
            const __nv_bfloat16* hb = &g_hb[dir][s & 1][0][0][0];
            #pragma unroll
            for (int q = 0; q < 16; q++) {        // plane 0 (hi)
                int i = lane + q * 32;
                int rloc  = (i >> 4) & 31;
                int ccc   = i & 15;
                int row   = mhalf * 32 + rloc;
                int gc16  = kq * 16 + ccc;
                const __nv_bfloat16* src = hb + (size_t)row * HIDN + gc16 * 8;
                uint32_t dst = smb + LS_A + row * 1024 + swz16(gc16, row) * 16;
                CP_ASYNC16(dst, src);
            }
            CP_COMMIT();
            #pragma unroll
            for (int q = 0; q < 16; q++) {        // plane 1 (lo)
                int i = lane + q * 32;
                int rloc  = (i >> 4) & 31;
                int ccc   = i & 15;
                int row   = mhalf * 32 + rloc;
                int gc16  = kq * 16 + ccc;
                const __nv_bfloat16* src = hb + (size_t)(BATCHN * HIDN)
                                             + (size_t)row * HIDN + gc16 * 8;
                uint32_t dst = smb + LS_A + 65536 + row * 1024 +
                               swz16(gc16, row) * 16;
                CP_ASYNC16(dst, src);
            }
            CP_COMMIT();
        }

        // ---- init accumulators from precomputed input projection ----
        float c[2][4][4];
        if (kq == 0) {
            #pragma unroll
            for (int mt = 0; mt < 2; mt++)
                #pragma unroll
                for (int half = 0; half < 2; half++) {
                    int b = mhalf * 32 + mt * 16 + qrow + half * 8;
                    const float* xzp = &g_xz[dir][s][b][slice * 32];
                    #pragma unroll
                    for (int nt = 0; nt < 4; nt++) {
                        float2 v = *(const float2*)&xzp[nt * 8 + qcol];
                        c[mt][nt][half * 2 + 0] = v.x;
                        c[mt][nt][half * 2 + 1] = v.y;
                    }
                }
        } else {
            #pragma unroll
            for (int mt = 0; mt < 2; mt++)
                #pragma unroll
                for (int nt = 0; nt < 4; nt++)
                    #pragma unroll
                    for (int e = 0; e < 4; e++) c[mt][nt][e] = 0.f;
        }

        // ---- MMA: phase A (hi plane) under WAIT1, phase B after WAIT0 ----
        if (s > 0) {
            CP_WAIT1();
            #pragma unroll 2
            for (int j = 0; j < 8; j++) {
                int gc = kq * 16 + j * 2;
                uint32_t ah[2][4], bh[4][2], bl[4][2];
                #pragma unroll
                for (int mt = 0; mt < 2; mt++) {
                    int row = mhalf * 32 + mt * 16 + a_row;
                    uint32_t oh = smb + LS_A + row * 1024 + swz16(gc + a_cad, row) * 16;
                    LDSM_X4(ah[mt][0], ah[mt][1], ah[mt][2], ah[mt][3], oh);
                }
                #pragma unroll
                for (int jn = 0; jn < 2; jn++) {
                    int row = jn * 16 + b_row;
                    uint32_t oh = smb + LS_B + row * 1024 + swz16(gc + b_cad, row) * 16;
                    LDSM_X4(bh[2*jn][0], bh[2*jn][1], bh[2*jn+1][0], bh[2*jn+1][1], oh);
                    LDSM_X4(bl[2*jn][0], bl[2*jn][1], bl[2*jn+1][0], bl[2*jn+1][1],
                            oh + 32768);
                }
                #pragma unroll
                for (int mt = 0; mt < 2; mt++)
                    #pragma unroll
                    for (int nt = 0; nt < 4; nt++) {
                        MMA_BF16(c[mt][nt], ah[mt], bh[nt]);
                        MMA_BF16(c[mt][nt], ah[mt], bl[nt]);
                    }
            }
            CP_WAIT0();
            #pragma unroll 2
            for (int j = 0; j < 8; j++) {
                int gc = kq * 16 + j * 2;
                uint32_t al[2][4], bh[4][2];
                #pragma unroll
                for (int mt = 0; mt < 2; mt++) {
                    int row = mhalf * 32 + mt * 16 + a_row;
                    uint32_t ol = smb + LS_A + 65536 + row * 1024 +
                                  swz16(gc + a_cad, row) * 16;
                    LDSM_X4(al[mt][0], al[mt][1], al[mt][2], al[mt][3], ol);
                }
                #pragma unroll
                for (int jn = 0; jn < 2; jn++) {
                    int row = jn * 16 + b_row;
                    uint32_t oh = smb + LS_B + row * 1024 + swz16(gc + b_cad, row) * 16;
                    LDSM_X4(bh[2*jn][0], bh[2*jn][1], bh[2*jn+1][0], bh[2*jn+1][1], oh);
                }
                #pragma unroll
                for (int mt = 0; mt < 2; mt++)
                    #pragma unroll
                    for (int nt = 0; nt < 4; nt++)
                        MMA_BF16(c[mt][nt], al[mt], bh[nt]);
            }
        }

        // ---- single-round: every warp stores partials to its kq buffer ----
        __syncthreads();
        {
            float* bp = spill + kq * 2176;   // [64][34]
            #pragma unroll
            for (int mt = 0; mt < 2; mt++)
                #pragma unroll
                for (int half = 0; half < 2; half++) {
                    int r = mhalf * 32 + mt * 16 + qrow + half * 8;
                    #pragma unroll
                    for (int nt = 0; nt < 4; nt++) {
                        float2 v;
                        v.x = c[mt][nt][half * 2 + 0];
                        v.y = c[mt][nt][half * 2 + 1];
                        *(float2*)&bp[r * 34 + nt * 8 + qcol] = v;
                    }
                }
        }
        __syncthreads();

        // ---- gates: 256 threads x 2 adjacent units, float2 reads ----
        {
            float2 z2[4];
            #pragma unroll
            for (int g = 0; g < 4; g++) {
                int off = gb * 34 + g * 8 + grp;
                float2 a0 = *(const float2*)&spill[off];
                float2 a1 = *(const float2*)&spill[2176 + off];
                float2 a2 = *(const float2*)&spill[4352 + off];
                float2 a3 = *(const float2*)&spill[6528 + off];
                z2[g].x = (a0.x + a1.x) + (a2.x + a3.x);
                z2[g].y = (a0.y + a1.y) + (a2.y + a3.y);
            }
            float hh[2];
            #pragma unroll
            for (int u = 0; u < 2; u++) {
                float zi = u ? z2[0].y : z2[0].x;
                float zf = u ? z2[1].y : z2[1].x;
                float zg = u ? z2[2].y : z2[2].x;
                float zo = u ? z2[3].y : z2[3].x;
                float gi = fsig(zi);
                float gf = fsig(zf);
                float gg = fmaxf(zg, 0.f);
                float go = fsig(zo);
                float cv = gf * cell[u] + gi * gg;
                cell[u] = cv;
                hh[u] = go * fmaxf(cv, 0.f);
            }
            __nv_bfloat162 vhi, vlo;
            vhi.x = __float2bfloat16(hh[0]);
            vhi.y = __float2bfloat16(hh[1]);
            vlo.x = __float2bfloat16(hh[0] - __bfloat162float(vhi.x));
            vlo.y = __float2bfloat16(hh[1] - __bfloat162float(vhi.y));
            int kk = slice * 8 + grp;
            int pp = (s + 1) & 1;
            *(__nv_bfloat162*)&g_hb[dir][pp][0][gb][kk] = vhi;
            *(__nv_bfloat162*)&g_hb[dir][pp][1][gb][kk] = vlo;
            if (s == TLEN - 1) {
                float2 vf; vf.x = hh[0]; vf.y = hh[1];
                *(float2*)&g_h[dir][0][gb][kk] = vf;
            }
        }

        if (s < TLEN - 1) {
            // release/acquire grid barrier (no L1-flushing threadfence)
            __syncthreads();
            if (tid == 0) {
                asm volatile("red.release.gpu.global.add.u32 [%0], %1;"
                             :: "l"(&g_bar), "r"(1u) : "memory");
                unsigned target = (unsigned)(s + 1) * nb;
                unsigned v;
                do {
                    asm volatile("ld.acquire.gpu.global.u32 %0, [%1];"
                                 : "=r"(v) : "l"(&g_bar) : "memory");
                } while (v < target);
            }
            __syncthreads();
        }
    }
}

// ---------------------------------------------------------------------------
// Kernel 3: dense + softmax
// ---------------------------------------------------------------------------
__global__ __launch_bounds__(320) void dense_kernel(
    const float* __restrict__ Wd, const float* __restrict__ bd,
    float* __restrict__ out)
{
    const int b = blockIdx.x;
    const int w = threadIdx.x >> 5, lane = threadIdx.x & 31;
    __shared__ float logits[NCLSN];

    float sum = 0.f;
    for (int k = lane; k < 2 * HIDN; k += 32) {
        float hv = (k < HIDN) ? g_h[0][0][b][k] : g_h[1][0][b][k - HIDN];
        sum = fmaf(hv, Wd[k * NCLSN + w], sum);
    }
    #pragma unroll
    for (int off = 16; off > 0; off >>= 1)
        sum += __shfl_down_sync(0xffffffffu, sum, off);
    if (lane == 0) logits[w] = sum + bd[w];
    __syncthreads();

    if (threadIdx.x == 0) {
        float mx = logits[0];
        #pragma unroll
        for (int n = 1; n < NCLSN; n++) mx = fmaxf(mx, logits[n]);
        float es[NCLSN], ssum = 0.f;
        #pragma unroll
        for (int n = 0; n < NCLSN; n++) { es[n] = expf(logits[n] - mx); ssum += es[n]; }
        float inv = 1.f / ssum;
        #pragma unroll
        for (int n = 0; n < NCLSN; n++) out[b * NCLSN + n] = es[n] * inv;
    }
}

// ---------------------------------------------------------------------------
extern "C" void kernel_launch(void* const* d_in, const int* in_sizes, int n_in,
                              void* d_out, int out_size)
{
    const int*   x    = (const int*)  d_in[0];
    const float* emb  = (const float*)d_in[1];
    const float* Wx_f = (const float*)d_in[2];
    const float* Wh_f = (const float*)d_in[3];
    const float* b_f  = (const float*)d_in[4];
    const float* Wx_b = (const float*)d_in[5];
    const float* Wh_b = (const float*)d_in[6];
    const float* b_b  = (const float*)d_in[7];
    const float* Wd   = (const float*)d_in[8];
    const float* bd   = (const float*)d_in[9];
    float* out = (float*)d_out;

    (void)in_sizes; (void)n_in; (void)out_size;

    cudaFuncSetAttribute(gemm_mma,
                         cudaFuncAttributeMaxDynamicSharedMemorySize, GT_SMEM);
    cudaFuncSetAttribute(lstm_kernel,
                         cudaFuncAttributeMaxDynamicSharedMemorySize, LSTM_SMEM_BYTES);

    prep_w<<<dim3(G4, 2), KPAD>>>(Wx_f, b_f, Wx_b, b_b);
    prep_wh<<<dim3(G4, 2), HIDN>>>(Wh_f, Wh_b);
    prep_a<<<MROWS, KPAD>>>(x, emb);
    gemm_mma<<<2 * 128 * 16, 256, GT_SMEM>>>();
    lstm_kernel<<<128, 256, LSTM_SMEM_BYTES>>>();
    dense_kernel<<<BATCHN, 320>>>(Wd, bd, out);
}

// round 12
// speedup vs baseline: 1.1320x; 1.1190x over previous
#include <cuda_runtime.h>
#include <cuda_bf16.h>
#include <math.h>
#include <stdint.h>

#define VOCABN 50000
#define EMBN   300
#define KPAD   320     // EMB padded to 10 chunks of 32
#define TLEN   256
#define HIDN   512
#define G4     2048    // 4*HID
#define NCLSN  10
#define BATCHN 64
#define MROWS  (TLEN*BATCHN)

// ---------------------------------------------------------------------------
// Device scratch
// ---------------------------------------------------------------------------
__device__ __align__(256) float g_xz[2][TLEN][BATCHN][G4]; // permuted gate cols
__device__ __align__(256) float g_h[2][2][BATCHN][HIDN];   // fp32 h (final step, for dense)
__device__ unsigned g_bar;                                 // grid barrier counter

__device__ __align__(256) __nv_bfloat16 g_Ahi[(size_t)MROWS * KPAD];
__device__ __align__(256) __nv_bfloat16 g_Alo[(size_t)MROWS * KPAD];
__device__ __align__(256) __nv_bfloat16 g_Bhi[(size_t)2 * G4 * KPAD];
__device__ __align__(256) __nv_bfloat16 g_Blo[(size_t)2 * G4 * KPAD];
__device__ __align__(256) float g_biasp[2 * G4];

// recurrence operands: h as bf16 (hi plane only now), Wh^T as bf16 hi/lo
__device__ __align__(256) __nv_bfloat16 g_hb[2][2][2][BATCHN][HIDN];   // [dir][pp][plane][b][k]
__device__ __align__(256) __nv_bfloat16 g_WhT[2][2][G4][HIDN];         // [dir][plane][p][k]

__device__ __forceinline__ int perm_src(int p) {
    return ((p >> 3) & 3) * HIDN + (p >> 5) * 8 + (p & 7);
}

__device__ __forceinline__ uint32_t smem_to_u32(const void* p) {
    uint32_t a;
    asm("{ .reg .u64 t; cvta.to.shared.u64 t, %1; cvt.u32.u64 %0, t; }"
        : "=r"(a) : "l"(p));
    return a;
}

// ---------------------------------------------------------------------------
// mma.sync / ldmatrix / cp.async helpers (baseline PTX, no 'a' features)
// ---------------------------------------------------------------------------
#define LDSM_X4(r0, r1, r2, r3, addr) \
    asm volatile("ldmatrix.sync.aligned.m8n8.x4.shared.b16 {%0,%1,%2,%3}, [%4];" \
        : "=r"(r0), "=r"(r1), "=r"(r2), "=r"(r3) : "r"(addr))

#define MMA_BF16(c, a, b) \
    asm volatile("mma.sync.aligned.m16n8k16.row.col.f32.bf16.bf16.f32 " \
        "{%0,%1,%2,%3}, {%4,%5,%6,%7}, {%8,%9}, {%0,%1,%2,%3};" \
        : "+f"((c)[0]), "+f"((c)[1]), "+f"((c)[2]), "+f"((c)[3]) \
        : "r"((a)[0]), "r"((a)[1]), "r"((a)[2]), "r"((a)[3]), \
          "r"((b)[0]), "r"((b)[1]))

#define CP_ASYNC16(dst, src) \
    asm volatile("cp.async.cg.shared.global [%0], [%1], 16;" \
        :: "r"(dst), "l"(src) : "memory")
#define CP_COMMIT() asm volatile("cp.async.commit_group;" ::: "memory")
#define CP_WAIT1()  asm volatile("cp.async.wait_group 1;" ::: "memory")
#define CP_WAIT0()  asm volatile("cp.async.wait_group 0;" ::: "memory")

// swizzle of a 16B-chunk index within a 1KB row (XOR low 3 bits with row&7)
__device__ __forceinline__ uint32_t swz16(uint32_t c16, uint32_t row) {
    return (c16 & ~7u) | ((c16 ^ row) & 7u);
}

__device__ __forceinline__ float fsig(float x) {
    return __fdividef(1.f, 1.f + __expf(-x));
}

// ---------------------------------------------------------------------------
// Prep kernels
// ---------------------------------------------------------------------------
__global__ __launch_bounds__(KPAD) void prep_w(
    const float* __restrict__ Wx_f, const float* __restrict__ b_f,
    const float* __restrict__ Wx_b, const float* __restrict__ b_b)
{
    int n = blockIdx.x, dir = blockIdx.y, k = threadIdx.x;
    if (n == 0 && dir == 0 && k == 0) g_bar = 0u;     // grid-barrier reset
    int src = perm_src(n);
    const float* Wx = dir ? Wx_b : Wx_f;
    float v = (k < EMBN) ? Wx[(size_t)k * G4 + src] : 0.f;
    __nv_bfloat16 hi = __float2bfloat16(v);
    __nv_bfloat16 lo = __float2bfloat16(v - __bfloat162float(hi));
    size_t idx = (size_t)(dir * G4 + n) * KPAD + k;
    g_Bhi[idx] = hi;
    g_Blo[idx] = lo;
    if (k == 0) g_biasp[dir * G4 + n] = (dir ? b_b : b_f)[src];
}

__global__ __launch_bounds__(KPAD) void prep_a(
    const int* __restrict__ x, const float* __restrict__ emb)
{
    int row = blockIdx.x;
    int t = row >> 6, b = row & 63;
    __shared__ int tok;
    if (threadIdx.x == 0) tok = x[b * TLEN + t];
    __syncthreads();
    int k = threadIdx.x;
    float v = (k < EMBN) ? emb[(size_t)tok * EMBN + k] : 0.f;
    __nv_bfloat16 hi = __float2bfloat16(v);
    __nv_bfloat16 lo = __float2bfloat16(v - __bfloat162float(hi));
    size_t idx = (size_t)row * KPAD + k;
    g_Ahi[idx] = hi;
    g_Alo[idx] = lo;
}

// Wh^T with gate-column permutation, bf16 hi/lo planes, k-contiguous rows
__global__ __launch_bounds__(HIDN) void prep_wh(
    const float* __restrict__ Wh_f, const float* __restrict__ Wh_b)
{
    int p = blockIdx.x, dir = blockIdx.y, k = threadIdx.x;
    int src = perm_src(p);
    float v = (dir ? Wh_b : Wh_f)[(size_t)k * G4 + src];
    __nv_bfloat16 hi = __float2bfloat16(v);
    __nv_bfloat16 lo = __float2bfloat16(v - __bfloat162float(hi));
    g_WhT[dir][0][p][k] = hi;
    g_WhT[dir][1][p][k] = lo;
}

// ---------------------------------------------------------------------------
// Tensor-core (mma.sync bf16x3) input projection (unchanged, verified 298us)
// ---------------------------------------------------------------------------
#define GT_STAGE 32768
#define GT_SMEM  (2 * GT_STAGE)
#define NCHUNK   10

__global__ __launch_bounds__(256, 2) void gemm_mma()
{
    extern __shared__ char sm[];
    const uint32_t smb = smem_to_u32(sm);
    const int tid = threadIdx.x, wid = tid >> 5, lane = tid & 31;

    const int ntile = blockIdx.x & 15;
    const int mtile = (blockIdx.x >> 4) & 127;
    const int dir   = blockIdx.x >> 11;
    const int m0 = mtile * 128, n0 = ntile * 128;

    const int mwarp = (wid >> 2) * 64;
    const int nwarp = (wid & 3) * 32;

    const int crow = tid >> 3;
    const int cc   = tid & 7;
    const __nv_bfloat16* srcA_base = (cc < 4) ? g_Ahi : g_Alo;
    const __nv_bfloat16* srcB_base = (cc < 4) ? g_Bhi : g_Blo;
    const int ksub = (cc & 3) * 8;

    const int a_row = (lane & 7) + ((lane >> 3) & 1) * 8;
    const int a_cad = (lane >> 4) & 1;
    const int b_row = (lane & 7) + ((lane >> 4) & 1) * 8;
    const int b_cad = (lane >> 3) & 1;

    float c[4][4][4];
    #pragma unroll
    for (int i = 0; i < 4; i++)
        #pragma unroll
        for (int j = 0; j < 4; j++)
            #pragma unroll
            for (int e = 0; e < 4; e++) c[i][j][e] = 0.f;

    #define ISSUE_COPY(kc, stage) do {                                         \
        uint32_t sA = smb + (stage) * GT_STAGE;                                \
        uint32_t sB = sA + 16384;                                              \
        _Pragma("unroll")                                                      \
        for (int q = 0; q < 4; q++) {                                          \
            int row = crow + q * 32;                                           \
            uint32_t dof = (uint32_t)row * 128 + ((cc ^ (row & 7)) * 16);      \
            const __nv_bfloat16* sa = srcA_base +                              \
                (size_t)(m0 + row) * KPAD + (kc) * 32 + ksub;                  \
            const __nv_bfloat16* sb = srcB_base +                              \
                (size_t)(dir * G4 + n0 + row) * KPAD + (kc) * 32 + ksub;       \
            CP_ASYNC16(sA + dof, sa);                                          \
            CP_ASYNC16(sB + dof, sb);                                          \
        }                                                                      \
        CP_COMMIT();                                                           \
    } while (0)

    ISSUE_COPY(0, 0);

    #pragma unroll 1
    for (int kc = 0; kc < NCHUNK; kc++) {
        if (kc + 1 < NCHUNK) {
            ISSUE_COPY(kc + 1, (kc + 1) & 1);
            CP_WAIT1();
        } else {
            CP_WAIT0();
        }
        __syncthreads();

        const uint32_t sA = smb + (kc & 1) * GT_STAGE;
        const uint32_t sB = sA + 16384;

        #pragma unroll
        for (int ks = 0; ks < 2; ks++) {
            uint32_t ah[4][4], al[4][4], bh[4][2], bl[4][2];
            #pragma unroll
            for (int mt = 0; mt < 4; mt++) {
                int row = mwarp + mt * 16 + a_row;
                int swzr = row & 7;
                uint32_t oh = sA + (uint32_t)row * 128 +
                              (((ks * 2 + a_cad)     ^ swzr) * 16);
                uint32_t ol = sA + (uint32_t)row * 128 +
                              (((4 + ks * 2 + a_cad) ^ swzr) * 16);
                LDSM_X4(ah[mt][0], ah[mt][1], ah[mt][2], ah[mt][3], oh);
                LDSM_X4(al[mt][0], al[mt][1], al[mt][2], al[mt][3], ol);
            }
            #pragma unroll
            for (int j = 0; j < 2; j++) {
                int row = nwarp + j * 16 + b_row;
                int swzr = row & 7;
                uint32_t oh = sB + (uint32_t)row * 128 +
                              (((ks * 2 + b_cad)     ^ swzr) * 16);
                uint32_t ol = sB + (uint32_t)row * 128 +
                              (((4 + ks * 2 + b_cad) ^ swzr) * 16);
                LDSM_X4(bh[2*j][0], bh[2*j][1], bh[2*j+1][0], bh[2*j+1][1], oh);
                LDSM_X4(bl[2*j][0], bl[2*j][1], bl[2*j+1][0], bl[2*j+1][1], ol);
            }
            #pragma unroll
            for (int mt = 0; mt < 4; mt++)
                #pragma unroll
                for (int nt = 0; nt < 4; nt++) {
                    MMA_BF16(c[mt][nt], ah[mt], bh[nt]);
                    MMA_BF16(c[mt][nt], ah[mt], bl[nt]);
                    MMA_BF16(c[mt][nt], al[mt], bh[nt]);
                }
        }
        __syncthreads();
    }

    const int qrow = lane >> 2;
    const int qcol = (lane & 3) * 2;
    #pragma unroll
    for (int nt = 0; nt < 4; nt++) {
        int coll = nwarp + nt * 8 + qcol;
        int col  = n0 + coll;
        float2 bv = *(const float2*)&g_biasp[dir * G4 + col];
        #pragma unroll
        for (int mt = 0; mt < 4; mt++) {
            #pragma unroll
            for (int half = 0; half < 2; half++) {
                int g = m0 + mwarp + mt * 16 + qrow + half * 8;
                int t = g >> 6, b = g & 63;
                int tout = dir ? (TLEN - 1 - t) : t;
                float2 v;
                v.x = c[mt][nt][half * 2 + 0] + bv.x;
                v.y = c[mt][nt][half * 2 + 1] + bv.y;
                *(float2*)&g_xz[dir][tout][b][col] = v;
            }
        }
    }
}

// ---------------------------------------------------------------------------
// Kernel 2: persistent bidirectional LSTM recurrence, mma.sync.
// NEW vs R11 (verified 1638us): h carried as bf16 HI PLANE ONLY.
//   z = hhi @ (Whhi + Whlo)  — Wh keeps full bf16x2 precision (smem-resident,
//   free), h quantization error ~2^-9 enters once per step. Expected final
//   rel_err ~1e-5 (budget 1e-3).
//   => MMA per k16: 3 -> 2; staging LDGSTS/thread: 32 -> 16; h L2 traffic
//   and h stores halved; single WAIT0 (no phase split).
// Everything else identical to R11.
// ---------------------------------------------------------------------------
#define LS_A     0                   // A hi plane: 64KB (rows b, 1KB each)
#define LS_B     131072              // B planes: 2 x 32KB (rows n, 1KB each)
#define LS_SPILL 196608              // 4 bufs x [64][34] fp32 = 4 x 8704
#define LSTM_SMEM_BYTES (196608 + 4 * 8704)   // 231424

__global__ __launch_bounds__(256, 1) void lstm_kernel()
{
    extern __shared__ char sm[];
    const uint32_t smb = smem_to_u32(sm);
    float* spill = (float*)(sm + LS_SPILL);

    const int tid   = threadIdx.x;
    const int wid   = tid >> 5, lane = tid & 31;
    const int dir   = blockIdx.x >> 6;
    const int slice = blockIdx.x & 63;

    const int mhalf = wid & 1;        // M half: rows mhalf*32..+31
    const int kq    = wid >> 1;       // K quarter: k kq*128..+127

    // ---- one-time: load Wh^T slice (hi/lo) into smem ----
    #pragma unroll
    for (int i = tid; i < 4096; i += 256) {       // 4096 16B chunks
        int plane = i >> 11;
        int row   = (i >> 6) & 31;
        int c16   = i & 63;
        const __nv_bfloat16* src = &g_WhT[dir][plane][slice * 32 + row][c16 * 8];
        uint32_t dst = smb + LS_B + plane * 32768 + row * 1024 + swz16(c16, row) * 16;
        CP_ASYNC16(dst, src);
    }
    CP_COMMIT();
    CP_WAIT0();
    __syncthreads();

    // ldmatrix lane geometry (verified)
    const int a_row = (lane & 7) + ((lane >> 3) & 1) * 8;
    const int a_cad = (lane >> 4) & 1;
    const int b_row = (lane & 7) + ((lane >> 4) & 1) * 8;
    const int b_cad = (lane >> 3) & 1;
    const int qrow  = lane >> 2;
    const int qcol  = (lane & 3) * 2;
    const unsigned nb = gridDim.x;

    // gate-stage mapping: thread -> (gb, grp) covering units grp, grp+1
    const int gb  = tid >> 2;
    const int grp = (tid & 3) * 2;
    float cell[2] = {0.f, 0.f};       // register cell state for the 2 units

    for (int s = 0; s < TLEN; s++) {
        // ---- stage this warp's A slice: hi plane only (16 chunks/thread) ----
        if (s > 0) {
            const __nv_bfloat16* hb = &g_hb[dir][s & 1][0][0][0];
            #pragma unroll
            for (int q = 0; q < 16; q++) {
                int i = lane + q * 32;
                int rloc  = (i >> 4) & 31;
                int ccc   = i & 15;
                int row   = mhalf * 32 + rloc;
                int gc16  = kq * 16 + ccc;
                const __nv_bfloat16* src = hb + (size_t)row * HIDN + gc16 * 8;
                uint32_t dst = smb + LS_A + row * 1024 + swz16(gc16, row) * 16;
                CP_ASYNC16(dst, src);
            }
            CP_COMMIT();
        }

        // ---- init accumulators from precomputed input projection ----
        float c[2][4][4];
        if (kq == 0) {
            #pragma unroll
            for (int mt = 0; mt < 2; mt++)
                #pragma unroll
                for (int half = 0; half < 2; half++) {
                    int b = mhalf * 32 + mt * 16 + qrow + half * 8;
                    const float* xzp = &g_xz[dir][s][b][slice * 32];
                    #pragma unroll
                    for (int nt = 0; nt < 4; nt++) {
                        float2 v = *(const float2*)&xzp[nt * 8 + qcol];
                        c[mt][nt][half * 2 + 0] = v.x;
                        c[mt][nt][half * 2 + 1] = v.y;
                    }
                }
        } else {
            #pragma unroll
            for (int mt = 0; mt < 2; mt++)
                #pragma unroll
                for (int nt = 0; nt < 4; nt++)
                    #pragma unroll
                    for (int e = 0; e < 4; e++) c[mt][nt][e] = 0.f;
        }

        // ---- MMA: hhi x (Bhi + Blo), single wait ----
        if (s > 0) {
            CP_WAIT0();
            #pragma unroll 2
            for (int j = 0; j < 8; j++) {
                int gc = kq * 16 + j * 2;
                uint32_t ah[2][4], bh[4][2], bl[4][2];
                #pragma unroll
                for (int mt = 0; mt < 2; mt++) {
                    int row = mhalf * 32 + mt * 16 + a_row;
                    uint32_t oh = smb + LS_A + row * 1024 + swz16(gc + a_cad, row) * 16;
                    LDSM_X4(ah[mt][0], ah[mt][1], ah[mt][2], ah[mt][3], oh);
                }
                #pragma unroll
                for (int jn = 0; jn < 2; jn++) {
                    int row = jn * 16 + b_row;
                    uint32_t oh = smb + LS_B + row * 1024 + swz16(gc + b_cad, row) * 16;
                    LDSM_X4(bh[2*jn][0], bh[2*jn][1], bh[2*jn+1][0], bh[2*jn+1][1], oh);
                    LDSM_X4(bl[2*jn][0], bl[2*jn][1], bl[2*jn+1][0], bl[2*jn+1][1],
                            oh + 32768);
                }
                #pragma unroll
                for (int mt = 0; mt < 2; mt++)
                    #pragma unroll
                    for (int nt = 0; nt < 4; nt++) {
                        MMA_BF16(c[mt][nt], ah[mt], bh[nt]);
                        MMA_BF16(c[mt][nt], ah[mt], bl[nt]);
                    }
            }
        }

        // ---- single-round: every warp stores partials to its kq buffer ----
        __syncthreads();
        {
            float* bp = spill + kq * 2176;   // [64][34]
            #pragma unroll
            for (int mt = 0; mt < 2; mt++)
                #pragma unroll
                for (int half = 0; half < 2; half++) {
                    int r = mhalf * 32 + mt * 16 + qrow + half * 8;
                    #pragma unroll
                    for (int nt = 0; nt < 4; nt++) {
                        float2 v;
                        v.x = c[mt][nt][half * 2 + 0];
                        v.y = c[mt][nt][half * 2 + 1];
                        *(float2*)&bp[r * 34 + nt * 8 + qcol] = v;
                    }
                }
        }
        __syncthreads();

        // ---- gates: 256 threads x 2 adjacent units, float2 reads ----
        {
            float2 z2[4];
            #pragma unroll
            for (int g = 0; g < 4; g++) {
                int off = gb * 34 + g * 8 + grp;
                float2 a0 = *(const float2*)&spill[off];
                float2 a1 = *(const float2*)&spill[2176 + off];
                float2 a2 = *(const float2*)&spill[4352 + off];
                float2 a3 = *(const float2*)&spill[6528 + off];
                z2[g].x = (a0.x + a1.x) + (a2.x + a3.x);
                z2[g].y = (a0.y + a1.y) + (a2.y + a3.y);
            }
            float hh[2];
            #pragma unroll
            for (int u = 0; u < 2; u++) {
                float zi = u ? z2[0].y : z2[0].x;
                float zf = u ? z2[1].y : z2[1].x;
                float zg = u ? z2[2].y : z2[2].x;
                float zo = u ? z2[3].y : z2[3].x;
                float gi = fsig(zi);
                float gf = fsig(zf);
                float gg = fmaxf(zg, 0.f);
                float go = fsig(zo);
                float cv = gf * cell[u] + gi * gg;
                cell[u] = cv;
                hh[u] = go * fmaxf(cv, 0.f);
            }
            __nv_bfloat162 vhi;
            vhi.x = __float2bfloat16(hh[0]);
            vhi.y = __float2bfloat16(hh[1]);
            int kk = slice * 8 + grp;
            int pp = (s + 1) & 1;
            *(__nv_bfloat162*)&g_hb[dir][pp][0][gb][kk] = vhi;
            if (s == TLEN - 1) {
                float2 vf; vf.x = hh[0]; vf.y = hh[1];
                *(float2*)&g_h[dir][0][gb][kk] = vf;
            }
        }

        if (s < TLEN - 1) {
            // release/acquire grid barrier (no L1-flushing threadfence)
            __syncthreads();
            if (tid == 0) {
                asm volatile("red.release.gpu.global.add.u32 [%0], %1;"
                             :: "l"(&g_bar), "r"(1u) : "memory");
                unsigned target = (unsigned)(s + 1) * nb;
                unsigned v;
                do {
                    asm volatile("ld.acquire.gpu.global.u32 %0, [%1];"
                                 : "=r"(v) : "l"(&g_bar) : "memory");
                } while (v < target);
            }
            __syncthreads();
        }
    }
}

// ---------------------------------------------------------------------------
// Kernel 3: dense + softmax
// ---------------------------------------------------------------------------
__global__ __launch_bounds__(320) void dense_kernel(
    const float* __restrict__ Wd, const float* __restrict__ bd,
    float* __restrict__ out)
{
    const int b = blockIdx.x;
    const int w = threadIdx.x >> 5, lane = threadIdx.x & 31;
    __shared__ float logits[NCLSN];

    float sum = 0.f;
    for (int k = lane; k < 2 * HIDN; k += 32) {
        float hv = (k < HIDN) ? g_h[0][0][b][k] : g_h[1][0][b][k - HIDN];
        sum = fmaf(hv, Wd[k * NCLSN + w], sum);
    }
    #pragma unroll
    for (int off = 16; off > 0; off >>= 1)
        sum += __shfl_down_sync(0xffffffffu, sum, off);
    if (lane == 0) logits[w] = sum + bd[w];
    __syncthreads();

    if (threadIdx.x == 0) {
        float mx = logits[0];
        #pragma unroll
        for (int n = 1; n < NCLSN; n++) mx = fmaxf(mx, logits[n]);
        float es[NCLSN], ssum = 0.f;
        #pragma unroll
        for (int n = 0; n < NCLSN; n++) { es[n] = expf(logits[n] - mx); ssum += es[n]; }
        float inv = 1.f / ssum;
        #pragma unroll
        for (int n = 0; n < NCLSN; n++) out[b * NCLSN + n] = es[n] * inv;
    }
}

// ---------------------------------------------------------------------------
extern "C" void kernel_launch(void* const* d_in, const int* in_sizes, int n_in,
                              void* d_out, int out_size)
{
    const int*   x    = (const int*)  d_in[0];
    const float* emb  = (const float*)d_in[1];
    const float* Wx_f = (const float*)d_in[2];
    const float* Wh_f = (const float*)d_in[3];
    const float* b_f  = (const float*)d_in[4];
    const float* Wx_b = (const float*)d_in[5];
    const float* Wh_b = (const float*)d_in[6];
    const float* b_b  = (const float*)d_in[7];
    const float* Wd   = (const float*)d_in[8];
    const float* bd   = (const float*)d_in[9];
    float* out = (float*)d_out;

    (void)in_sizes; (void)n_in; (void)out_size;

    cudaFuncSetAttribute(gemm_mma,
                         cudaFuncAttributeMaxDynamicSharedMemorySize, GT_SMEM);
    cudaFuncSetAttribute(lstm_kernel,
                         cudaFuncAttributeMaxDynamicSharedMemorySize, LSTM_SMEM_BYTES);

    prep_w<<<dim3(G4, 2), KPAD>>>(Wx_f, b_f, Wx_b, b_b);
    prep_wh<<<dim3(G4, 2), HIDN>>>(Wh_f, Wh_b);
    prep_a<<<MROWS, KPAD>>>(x, emb);
    gemm_mma<<<2 * 128 * 16, 256, GT_SMEM>>>();
    lstm_kernel<<<128, 256, LSTM_SMEM_BYTES>>>();
    dense_kernel<<<BATCHN, 320>>>(Wd, bd, out);
}

// round 13
// speedup vs baseline: 1.2463x; 1.1010x over previous
#include <cuda_runtime.h>
#include <cuda_bf16.h>
#include <math.h>
#include <stdint.h>

#define VOCABN 50000
#define EMBN   300
#define KPAD   320     // EMB padded to 10 chunks of 32
#define TLEN   256
#define HIDN   512
#define G4     2048    // 4*HID
#define NCLSN  10
#define BATCHN 64
#define MROWS  (TLEN*BATCHN)

// ---------------------------------------------------------------------------
// Device scratch
// ---------------------------------------------------------------------------
__device__ __align__(256) float g_xz[2][TLEN][BATCHN][G4]; // permuted gate cols
__device__ __align__(256) float g_h[2][2][BATCHN][HIDN];   // fp32 h (final step, for dense)
__device__ unsigned g_bar;                                 // grid barrier counter

__device__ __align__(256) __nv_bfloat16 g_Ahi[(size_t)MROWS * KPAD];
__device__ __align__(256) __nv_bfloat16 g_Alo[(size_t)MROWS * KPAD];
__device__ __align__(256) __nv_bfloat16 g_Bhi[(size_t)2 * G4 * KPAD];
__device__ __align__(256) __nv_bfloat16 g_Blo[(size_t)2 * G4 * KPAD];
__device__ __align__(256) float g_biasp[2 * G4];

// recurrence operands: h as bf16 (hi plane only), Wh^T as bf16 (hi plane only)
__device__ __align__(256) __nv_bfloat16 g_hb[2][2][2][BATCHN][HIDN];   // [dir][pp][plane][b][k]
__device__ __align__(256) __nv_bfloat16 g_WhT[2][2][G4][HIDN];         // [dir][plane][p][k]

__device__ __forceinline__ int perm_src(int p) {
    return ((p >> 3) & 3) * HIDN + (p >> 5) * 8 + (p & 7);
}

__device__ __forceinline__ uint32_t smem_to_u32(const void* p) {
    uint32_t a;
    asm("{ .reg .u64 t; cvta.to.shared.u64 t, %1; cvt.u32.u64 %0, t; }"
        : "=r"(a) : "l"(p));
    return a;
}

// ---------------------------------------------------------------------------
// mma.sync / ldmatrix / cp.async helpers (baseline PTX, no 'a' features)
// ---------------------------------------------------------------------------
#define LDSM_X4(r0, r1, r2, r3, addr) \
    asm volatile("ldmatrix.sync.aligned.m8n8.x4.shared.b16 {%0,%1,%2,%3}, [%4];" \
        : "=r"(r0), "=r"(r1), "=r"(r2), "=r"(r3) : "r"(addr))

#define MMA_BF16(c, a, b) \
    asm volatile("mma.sync.aligned.m16n8k16.row.col.f32.bf16.bf16.f32 " \
        "{%0,%1,%2,%3}, {%4,%5,%6,%7}, {%8,%9}, {%0,%1,%2,%3};" \
        : "+f"((c)[0]), "+f"((c)[1]), "+f"((c)[2]), "+f"((c)[3]) \
        : "r"((a)[0]), "r"((a)[1]), "r"((a)[2]), "r"((a)[3]), \
          "r"((b)[0]), "r"((b)[1]))

#define CP_ASYNC16(dst, src) \
    asm volatile("cp.async.cg.shared.global [%0], [%1], 16;" \
        :: "r"(dst), "l"(src) : "memory")
#define CP_COMMIT() asm volatile("cp.async.commit_group;" ::: "memory")
#define CP_WAIT1()  asm volatile("cp.async.wait_group 1;" ::: "memory")
#define CP_WAIT0()  asm volatile("cp.async.wait_group 0;" ::: "memory")

// swizzle of a 16B-chunk index within a 1KB row (XOR low 3 bits with row&7)
__device__ __forceinline__ uint32_t swz16(uint32_t c16, uint32_t row) {
    return (c16 & ~7u) | ((c16 ^ row) & 7u);
}

__device__ __forceinline__ float fsig(float x) {
    return __fdividef(1.f, 1.f + __expf(-x));
}

// ---------------------------------------------------------------------------
// Prep kernels
// ---------------------------------------------------------------------------
__global__ __launch_bounds__(KPAD) void prep_w(
    const float* __restrict__ Wx_f, const float* __restrict__ b_f,
    const float* __restrict__ Wx_b, const float* __restrict__ b_b)
{
    int n = blockIdx.x, dir = blockIdx.y, k = threadIdx.x;
    if (n == 0 && dir == 0 && k == 0) g_bar = 0u;     // grid-barrier reset
    int src = perm_src(n);
    const float* Wx = dir ? Wx_b : Wx_f;
    float v = (k < EMBN) ? Wx[(size_t)k * G4 + src] : 0.f;
    __nv_bfloat16 hi = __float2bfloat16(v);
    __nv_bfloat16 lo = __float2bfloat16(v - __bfloat162float(hi));
    size_t idx = (size_t)(dir * G4 + n) * KPAD + k;
    g_Bhi[idx] = hi;
    g_Blo[idx] = lo;
    if (k == 0) g_biasp[dir * G4 + n] = (dir ? b_b : b_f)[src];
}

__global__ __launch_bounds__(KPAD) void prep_a(
    const int* __restrict__ x, const float* __restrict__ emb)
{
    int row = blockIdx.x;
    int t = row >> 6, b = row & 63;
    __shared__ int tok;
    if (threadIdx.x == 0) tok = x[b * TLEN + t];
    __syncthreads();
    int k = threadIdx.x;
    float v = (k < EMBN) ? emb[(size_t)tok * EMBN + k] : 0.f;
    __nv_bfloat16 hi = __float2bfloat16(v);
    __nv_bfloat16 lo = __float2bfloat16(v - __bfloat162float(hi));
    size_t idx = (size_t)row * KPAD + k;
    g_Ahi[idx] = hi;
    g_Alo[idx] = lo;
}

// Wh^T with gate-column permutation, bf16 (round-to-nearest), k-contiguous rows
__global__ __launch_bounds__(HIDN) void prep_wh(
    const float* __restrict__ Wh_f, const float* __restrict__ Wh_b)
{
    int p = blockIdx.x, dir = blockIdx.y, k = threadIdx.x;
    int src = perm_src(p);
    float v = (dir ? Wh_b : Wh_f)[(size_t)k * G4 + src];
    g_WhT[dir][0][p][k] = __float2bfloat16(v);
}

// ---------------------------------------------------------------------------
// Tensor-core (mma.sync bf16x3) input projection (unchanged, verified 298us)
// ---------------------------------------------------------------------------
#define GT_STAGE 32768
#define GT_SMEM  (2 * GT_STAGE)
#define NCHUNK   10

__global__ __launch_bounds__(256, 2) void gemm_mma()
{
    extern __shared__ char sm[];
    const uint32_t smb = smem_to_u32(sm);
    const int tid = threadIdx.x, wid = tid >> 5, lane = tid & 31;

    const int ntile = blockIdx.x & 15;
    const int mtile = (blockIdx.x >> 4) & 127;
    const int dir   = blockIdx.x >> 11;
    const int m0 = mtile * 128, n0 = ntile * 128;

    const int mwarp = (wid >> 2) * 64;
    const int nwarp = (wid & 3) * 32;

    const int crow = tid >> 3;
    const int cc   = tid & 7;
    const __nv_bfloat16* srcA_base = (cc < 4) ? g_Ahi : g_Alo;
    const __nv_bfloat16* srcB_base = (cc < 4) ? g_Bhi : g_Blo;
    const int ksub = (cc & 3) * 8;

    const int a_row = (lane & 7) + ((lane >> 3) & 1) * 8;
    const int a_cad = (lane >> 4) & 1;
    const int b_row = (lane & 7) + ((lane >> 4) & 1) * 8;
    const int b_cad = (lane >> 3) & 1;

    float c[4][4][4];
    #pragma unroll
    for (int i = 0; i < 4; i++)
        #pragma unroll
        for (int j = 0; j < 4; j++)
            #pragma unroll
            for (int e = 0; e < 4; e++) c[i][j][e] = 0.f;

    #define ISSUE_COPY(kc, stage) do {                                         \
        uint32_t sA = smb + (stage) * GT_STAGE;                                \
        uint32_t sB = sA + 16384;                                              \
        _Pragma("unroll")                                                      \
        for (int q = 0; q < 4; q++) {                                          \
            int row = crow + q * 32;                                           \
            uint32_t dof = (uint32_t)row * 128 + ((cc ^ (row & 7)) * 16);      \
            const __nv_bfloat16* sa = srcA_base +                              \
                (size_t)(m0 + row) * KPAD + (kc) * 32 + ksub;                  \
            const __nv_bfloat16* sb = srcB_base +                              \
                (size_t)(dir * G4 + n0 + row) * KPAD + (kc) * 32 + ksub;       \
            CP_ASYNC16(sA + dof, sa);                                          \
            CP_ASYNC16(sB + dof, sb);                                          \
        }                                                                      \
        CP_COMMIT();                                                           \
    } while (0)

    ISSUE_COPY(0, 0);

    #pragma unroll 1
    for (int kc = 0; kc < NCHUNK; kc++) {
        if (kc + 1 < NCHUNK) {
            ISSUE_COPY(kc + 1, (kc + 1) & 1);
            CP_WAIT1();
        } else {
            CP_WAIT0();
        }
        __syncthreads();

        const uint32_t sA = smb + (kc & 1) * GT_STAGE;
        const uint32_t sB = sA + 16384;

        #pragma unroll
        for (int ks = 0; ks < 2; ks++) {
            uint32_t ah[4][4], al[4][4], bh[4][2], bl[4][2];
            #pragma unroll
            for (int mt = 0; mt < 4; mt++) {
                int row = mwarp + mt * 16 + a_row;
                int swzr = row & 7;
                uint32_t oh = sA + (uint32_t)row * 128 +
                              (((ks * 2 + a_cad)     ^ swzr) * 16);
                uint32_t ol = sA + (uint32_t)row * 128 +
                              (((4 + ks * 2 + a_cad) ^ swzr) * 16);
                LDSM_X4(ah[mt][0], ah[mt][1], ah[mt][2], ah[mt][3], oh);
                LDSM_X4(al[mt][0], al[mt][1], al[mt][2], al[mt][3], ol);
            }
            #pragma unroll
            for (int j = 0; j < 2; j++) {
                int row = nwarp + j * 16 + b_row;
                int swzr = row & 7;
                uint32_t oh = sB + (uint32_t)row * 128 +
                              (((ks * 2 + b_cad)     ^ swzr) * 16);
                uint32_t ol = sB + (uint32_t)row * 128 +
                              (((4 + ks * 2 + b_cad) ^ swzr) * 16);
                LDSM_X4(bh[2*j][0], bh[2*j][1], bh[2*j+1][0], bh[2*j+1][1], oh);
                LDSM_X4(bl[2*j][0], bl[2*j][1], bl[2*j+1][0], bl[2*j+1][1], ol);
            }
            #pragma unroll
            for (int mt = 0; mt < 4; mt++)
                #pragma unroll
                for (int nt = 0; nt < 4; nt++) {
                    MMA_BF16(c[mt][nt], ah[mt], bh[nt]);
                    MMA_BF16(c[mt][nt], ah[mt], bl[nt]);
                    MMA_BF16(c[mt][nt], al[mt], bh[nt]);
                }
        }
        __syncthreads();
    }

    const int qrow = lane >> 2;
    const int qcol = (lane & 3) * 2;
    #pragma unroll
    for (int nt = 0; nt < 4; nt++) {
        int coll = nwarp + nt * 8 + qcol;
        int col  = n0 + coll;
        float2 bv = *(const float2*)&g_biasp[dir * G4 + col];
        #pragma unroll
        for (int mt = 0; mt < 4; mt++) {
            #pragma unroll
            for (int half = 0; half < 2; half++) {
                int g = m0 + mwarp + mt * 16 + qrow + half * 8;
                int t = g >> 6, b = g & 63;
                int tout = dir ? (TLEN - 1 - t) : t;
                float2 v;
                v.x = c[mt][nt][half * 2 + 0] + bv.x;
                v.y = c[mt][nt][half * 2 + 1] + bv.y;
                *(float2*)&g_xz[dir][tout][b][col] = v;
            }
        }
    }
}

// ---------------------------------------------------------------------------
// Kernel 2: persistent bidirectional LSTM recurrence, mma.sync.
// NEW vs R12 (verified 1464us): PURE bf16 recurrence — Wh also hi plane only.
//   z = h_bf16 @ Wh_bf16. Calibration: h-only quantization gave rel_err
//   4.2e-6; both operands predicted ~1e-5 (budget 1e-3).
//   => MMA per k16: 2 -> 1; B LDSM halved; Wh smem 64KB -> 32KB.
// Everything else identical to R12.
// ---------------------------------------------------------------------------
#define LS_A     0                   // A hi plane: 64KB (rows b, 1KB each)
#define LS_B     65536               // B hi plane: 32KB (rows n, 1KB each)
#define LS_SPILL 98304               // 4 bufs x [64][34] fp32 = 4 x 8704
#define LSTM_SMEM_BYTES (98304 + 4 * 8704)   // 133120

__global__ __launch_bounds__(256, 1) void lstm_kernel()
{
    extern __shared__ char sm[];
    const uint32_t smb = smem_to_u32(sm);
    float* spill = (float*)(sm + LS_SPILL);

    const int tid   = threadIdx.x;
    const int wid   = tid >> 5, lane = tid & 31;
    const int dir   = blockIdx.x >> 6;
    const int slice = blockIdx.x & 63;

    const int mhalf = wid & 1;        // M half: rows mhalf*32..+31
    const int kq    = wid >> 1;       // K quarter: k kq*128..+127

    // ---- one-time: load Wh^T slice (hi plane) into smem ----
    #pragma unroll
    for (int i = tid; i < 2048; i += 256) {       // 2048 16B chunks
        int row = (i >> 6) & 31;
        int c16 = i & 63;
        const __nv_bfloat16* src = &g_WhT[dir][0][slice * 32 + row][c16 * 8];
        uint32_t dst = smb + LS_B + row * 1024 + swz16(c16, row) * 16;
        CP_ASYNC16(dst, src);
    }
    CP_COMMIT();
    CP_WAIT0();
    __syncthreads();

    // ldmatrix lane geometry (verified)
    const int a_row = (lane & 7) + ((lane >> 3) & 1) * 8;
    const int a_cad = (lane >> 4) & 1;
    const int b_row = (lane & 7) + ((lane >> 4) & 1) * 8;
    const int b_cad = (lane >> 3) & 1;
    const int qrow  = lane >> 2;
    const int qcol  = (lane & 3) * 2;
    const unsigned nb = gridDim.x;

    // gate-stage mapping: thread -> (gb, grp) covering units grp, grp+1
    const int gb  = tid >> 2;
    const int grp = (tid & 3) * 2;
    float cell[2] = {0.f, 0.f};       // register cell state for the 2 units

    for (int s = 0; s < TLEN; s++) {
        // ---- stage this warp's A slice: hi plane only (16 chunks/thread) ----
        if (s > 0) {
            const __nv_bfloat16* hb = &g_hb[dir][s & 1][0][0][0];
            #pragma unroll
            for (int q = 0; q < 16; q++) {
                int i = lane + q * 32;
                int rloc  = (i >> 4) & 31;
                int ccc   = i & 15;
                int row   = mhalf * 32 + rloc;
                int gc16  = kq * 16 + ccc;
                const __nv_bfloat16* src = hb + (size_t)row * HIDN + gc16 * 8;
                uint32_t dst = smb + LS_A + row * 1024 + swz16(gc16, row) * 16;
                CP_ASYNC16(dst, src);
            }
            CP_COMMIT();
        }

        // ---- init accumulators from precomputed input projection ----
        float c[2][4][4];
        if (kq == 0) {
            #pragma unroll
            for (int mt = 0; mt < 2; mt++)
                #pragma unroll
                for (int half = 0; half < 2; half++) {
                    int b = mhalf * 32 + mt * 16 + qrow + half * 8;
                    const float* xzp = &g_xz[dir][s][b][slice * 32];
                    #pragma unroll
                    for (int nt = 0; nt < 4; nt++) {
                        float2 v = *(const float2*)&xzp[nt * 8 + qcol];
                        c[mt][nt][half * 2 + 0] = v.x;
                        c[mt][nt][half * 2 + 1] = v.y;
                    }
                }
        } else {
            #pragma unroll
            for (int mt = 0; mt < 2; mt++)
                #pragma unroll
                for (int nt = 0; nt < 4; nt++)
                    #pragma unroll
                    for (int e = 0; e < 4; e++) c[mt][nt][e] = 0.f;
        }

        // ---- MMA: pure bf16, single wait ----
        if (s > 0) {
            CP_WAIT0();
            #pragma unroll 2
            for (int j = 0; j < 8; j++) {
                int gc = kq * 16 + j * 2;
                uint32_t ah[2][4], bh[4][2];
                #pragma unroll
                for (int mt = 0; mt < 2; mt++) {
                    int row = mhalf * 32 + mt * 16 + a_row;
                    uint32_t oh = smb + LS_A + row * 1024 + swz16(gc + a_cad, row) * 16;
                    LDSM_X4(ah[mt][0], ah[mt][1], ah[mt][2], ah[mt][3], oh);
                }
                #pragma unroll
                for (int jn = 0; jn < 2; jn++) {
                    int row = jn * 16 + b_row;
                    uint32_t oh = smb + LS_B + row * 1024 + swz16(gc + b_cad, row) * 16;
                    LDSM_X4(bh[2*jn][0], bh[2*jn][1], bh[2*jn+1][0], bh[2*jn+1][1], oh);
                }
                #pragma unroll
                for (int mt = 0; mt < 2; mt++)
                    #pragma unroll
                    for (int nt = 0; nt < 4; nt++)
                        MMA_BF16(c[mt][nt], ah[mt], bh[nt]);
            }
        }

        // ---- single-round: every warp stores partials to its kq buffer ----
        __syncthreads();
        {
            float* bp = spill + kq * 2176;   // [64][34]
            #pragma unroll
            for (int mt = 0; mt < 2; mt++)
                #pragma unroll
                for (int half = 0; half < 2; half++) {
                    int r = mhalf * 32 + mt * 16 + qrow + half * 8;
                    #pragma unroll
                    for (int nt = 0; nt < 4; nt++) {
                        float2 v;
                        v.x = c[mt][nt][half * 2 + 0];
                        v.y = c[mt][nt][half * 2 + 1];
                        *(float2*)&bp[r * 34 + nt * 8 + qcol] = v;
                    }
                }
        }
        __syncthreads();

        // ---- gates: 256 threads x 2 adjacent units, float2 reads ----
        {
            float2 z2[4];
            #pragma unroll
            for (int g = 0; g < 4; g++) {
                int off = gb * 34 + g * 8 + grp;
                float2 a0 = *(const float2*)&spill[off];
                float2 a1 = *(const float2*)&spill[2176 + off];
                float2 a2 = *(const float2*)&spill[4352 + off];
                float2 a3 = *(const float2*)&spill[6528 + off];
                z2[g].x = (a0.x + a1.x) + (a2.x + a3.x);
                z2[g].y = (a0.y + a1.y) + (a2.y + a3.y);
            }
            float hh[2];
            #pragma unroll
            for (int u = 0; u < 2; u++) {
                float zi = u ? z2[0].y : z2[0].x;
                float zf = u ? z2[1].y : z2[1].x;
                float zg = u ? z2[2].y : z2[2].x;
                float zo = u ? z2[3].y : z2[3].x;
                float gi = fsig(zi);
                float gf = fsig(zf);
                float gg = fmaxf(zg, 0.f);
                float go = fsig(zo);
                float cv = gf * cell[u] + gi * gg;
                cell[u] = cv;
                hh[u] = go * fmaxf(cv, 0.f);
            }
            __nv_bfloat162 vhi;
            vhi.x = __float2bfloat16(hh[0]);
            vhi.y = __float2bfloat16(hh[1]);
            int kk = slice * 8 + grp;
            int pp = (s + 1) & 1;
            *(__nv_bfloat162*)&g_hb[dir][pp][0][gb][kk] = vhi;
            if (s == TLEN - 1) {
                float2 vf; vf.x = hh[0]; vf.y = hh[1];
                *(float2*)&g_h[dir][0][gb][kk] = vf;
            }
        }

        if (s < TLEN - 1) {
            // release/acquire grid barrier (no L1-flushing threadfence)
            __syncthreads();
            if (tid == 0) {
                asm volatile("red.release.gpu.global.add.u32 [%0], %1;"
                             :: "l"(&g_bar), "r"(1u) : "memory");
                unsigned target = (unsigned)(s + 1) * nb;
                unsigned v;
                do {
                    asm volatile("ld.acquire.gpu.global.u32 %0, [%1];"
                                 : "=r"(v) : "l"(&g_bar) : "memory");
                } while (v < target);
            }
            __syncthreads();
        }
    }
}

// ---------------------------------------------------------------------------
// Kernel 3: dense + softmax
// ---------------------------------------------------------------------------
__global__ __launch_bounds__(320) void dense_kernel(
    const float* __restrict__ Wd, const float* __restrict__ bd,
    float* __restrict__ out)
{
    const int b = blockIdx.x;
    const int w = threadIdx.x >> 5, lane = threadIdx.x & 31;
    __shared__ float logits[NCLSN];

    float sum = 0.f;
    for (int k = lane; k < 2 * HIDN; k += 32) {
        float hv = (k < HIDN) ? g_h[0][0][b][k] : g_h[1][0][b][k - HIDN];
        sum = fmaf(hv, Wd[k * NCLSN + w], sum);
    }
    #pragma unroll
    for (int off = 16; off > 0; off >>= 1)
        sum += __shfl_down_sync(0xffffffffu, sum, off);
    if (lane == 0) logits[w] = sum + bd[w];
    __syncthreads();

    if (threadIdx.x == 0) {
        float mx = logits[0];
        #pragma unroll
        for (int n = 1; n < NCLSN; n++) mx = fmaxf(mx, logits[n]);
        float es[NCLSN], ssum = 0.f;
        #pragma unroll
        for (int n = 0; n < NCLSN; n++) { es[n] = expf(logits[n] - mx); ssum += es[n]; }
        float inv = 1.f / ssum;
        #pragma unroll
        for (int n = 0; n < NCLSN; n++) out[b * NCLSN + n] = es[n] * inv;
    }
}

// ---------------------------------------------------------------------------
extern "C" void kernel_launch(void* const* d_in, const int* in_sizes, int n_in,
                              void* d_out, int out_size)
{
    const int*   x    = (const int*)  d_in[0];
    const float* emb  = (const float*)d_in[1];
    const float* Wx_f = (const float*)d_in[2];
    const float* Wh_f = (const float*)d_in[3];
    const float* b_f  = (const float*)d_in[4];
    const float* Wx_b = (const float*)d_in[5];
    const float* Wh_b = (const float*)d_in[6];
    const float* b_b  = (const float*)d_in[7];
    const float* Wd   = (const float*)d_in[8];
    const float* bd   = (const float*)d_in[9];
    float* out = (float*)d_out;

    (void)in_sizes; (void)n_in; (void)out_size;

    cudaFuncSetAttribute(gemm_mma,
                         cudaFuncAttributeMaxDynamicSharedMemorySize, GT_SMEM);
    cudaFuncSetAttribute(lstm_kernel,
                         cudaFuncAttributeMaxDynamicSharedMemorySize, LSTM_SMEM_BYTES);

    prep_w<<<dim3(G4, 2), KPAD>>>(Wx_f, b_f, Wx_b, b_b);
    prep_wh<<<dim3(G4, 2), HIDN>>>(Wh_f, Wh_b);
    prep_a<<<MROWS, KPAD>>>(x, emb);
    gemm_mma<<<2 * 128 * 16, 256, GT_SMEM>>>();
    lstm_kernel<<<128, 256, LSTM_SMEM_BYTES>>>();
    dense_kernel<<<BATCHN, 320>>>(Wd, bd, out);
}

// round 14
// speedup vs baseline: 1.4132x; 1.1339x over previous
#include <cuda_runtime.h>
#include <cuda_bf16.h>
#include <math.h>
#include <stdint.h>

#define VOCABN 50000
#define EMBN   300
#define KPAD   320     // EMB padded to 10 chunks of 32
#define TLEN   256
#define HIDN   512
#define G4     2048    // 4*HID
#define NCLSN  10
#define BATCHN 64
#define MROWS  (TLEN*BATCHN)

// ---------------------------------------------------------------------------
// Device scratch
// ---------------------------------------------------------------------------
__device__ __align__(256) float g_xz[2][TLEN][BATCHN][G4]; // permuted gate cols
__device__ __align__(256) float g_h[2][2][BATCHN][HIDN];   // fp32 h (final step, for dense)
__device__ unsigned g_bar;                                 // grid barrier counter

__device__ __align__(256) __nv_bfloat16 g_Ahi[(size_t)MROWS * KPAD];
__device__ __align__(256) __nv_bfloat16 g_Bhi[(size_t)2 * G4 * KPAD];
__device__ __align__(256) float g_biasp[2 * G4];

// recurrence operands: h as bf16 (hi plane only), Wh^T as bf16 (hi plane only)
__device__ __align__(256) __nv_bfloat16 g_hb[2][2][2][BATCHN][HIDN];   // [dir][pp][plane][b][k]
__device__ __align__(256) __nv_bfloat16 g_WhT[2][2][G4][HIDN];         // [dir][plane][p][k]

__device__ __forceinline__ int perm_src(int p) {
    return ((p >> 3) & 3) * HIDN + (p >> 5) * 8 + (p & 7);
}

__device__ __forceinline__ uint32_t smem_to_u32(const void* p) {
    uint32_t a;
    asm("{ .reg .u64 t; cvta.to.shared.u64 t, %1; cvt.u32.u64 %0, t; }"
        : "=r"(a) : "l"(p));
    return a;
}

// ---------------------------------------------------------------------------
// mma.sync / ldmatrix / cp.async helpers (baseline PTX, no 'a' features)
// ---------------------------------------------------------------------------
#define LDSM_X4(r0, r1, r2, r3, addr) \
    asm volatile("ldmatrix.sync.aligned.m8n8.x4.shared.b16 {%0,%1,%2,%3}, [%4];" \
        : "=r"(r0), "=r"(r1), "=r"(r2), "=r"(r3) : "r"(addr))

#define MMA_BF16(c, a, b) \
    asm volatile("mma.sync.aligned.m16n8k16.row.col.f32.bf16.bf16.f32 " \
        "{%0,%1,%2,%3}, {%4,%5,%6,%7}, {%8,%9}, {%0,%1,%2,%3};" \
        : "+f"((c)[0]), "+f"((c)[1]), "+f"((c)[2]), "+f"((c)[3]) \
        : "r"((a)[0]), "r"((a)[1]), "r"((a)[2]), "r"((a)[3]), \
          "r"((b)[0]), "r"((b)[1]))

#define CP_ASYNC16(dst, src) \
    asm volatile("cp.async.cg.shared.global [%0], [%1], 16;" \
        :: "r"(dst), "l"(src) : "memory")
#define CP_COMMIT() asm volatile("cp.async.commit_group;" ::: "memory")
#define CP_WAIT1()  asm volatile("cp.async.wait_group 1;" ::: "memory")
#define CP_WAIT0()  asm volatile("cp.async.wait_group 0;" ::: "memory")

// swizzle of a 16B-chunk index within a 1KB row (XOR low 3 bits with row&7)
__device__ __forceinline__ uint32_t swz16(uint32_t c16, uint32_t row) {
    return (c16 & ~7u) | ((c16 ^ row) & 7u);
}

__device__ __forceinline__ float fsig(float x) {
    return __fdividef(1.f, 1.f + __expf(-x));
}

// ---------------------------------------------------------------------------
// Prep kernels (bf16 round-to-nearest; lo planes no longer produced)
// ---------------------------------------------------------------------------
__global__ __launch_bounds__(KPAD) void prep_w(
    const float* __restrict__ Wx_f, const float* __restrict__ b_f,
    const float* __restrict__ Wx_b, const float* __restrict__ b_b)
{
    int n = blockIdx.x, dir = blockIdx.y, k = threadIdx.x;
    if (n == 0 && dir == 0 && k == 0) g_bar = 0u;     // grid-barrier reset
    int src = perm_src(n);
    const float* Wx = dir ? Wx_b : Wx_f;
    float v = (k < EMBN) ? Wx[(size_t)k * G4 + src] : 0.f;
    g_Bhi[(size_t)(dir * G4 + n) * KPAD + k] = __float2bfloat16(v);
    if (k == 0) g_biasp[dir * G4 + n] = (dir ? b_b : b_f)[src];
}

__global__ __launch_bounds__(KPAD) void prep_a(
    const int* __restrict__ x, const float* __restrict__ emb)
{
    int row = blockIdx.x;
    int t = row >> 6, b = row & 63;
    __shared__ int tok;
    if (threadIdx.x == 0) tok = x[b * TLEN + t];
    __syncthreads();
    int k = threadIdx.x;
    float v = (k < EMBN) ? emb[(size_t)tok * EMBN + k] : 0.f;
    g_Ahi[(size_t)row * KPAD + k] = __float2bfloat16(v);
}

// Wh^T with gate-column permutation, bf16, k-contiguous rows
__global__ __launch_bounds__(HIDN) void prep_wh(
    const float* __restrict__ Wh_f, const float* __restrict__ Wh_b)
{
    int p = blockIdx.x, dir = blockIdx.y, k = threadIdx.x;
    int src = perm_src(p);
    float v = (dir ? Wh_b : Wh_f)[(size_t)k * G4 + src];
    g_WhT[dir][0][p][k] = __float2bfloat16(v);
}

// ---------------------------------------------------------------------------
// Tensor-core input projection — NOW PURE bf16 (xz = Ahi @ Bhi^T + bias).
// Error model calibrated in R12/R13: one-shot z-perturbation ~2^-10 rel,
// heavily attenuated through gates; predicted output delta ≲1e-5.
// Staging copies hi planes only (cc<4): LDGSTS + smem traffic halve.
// MMAs per ks: 12 -> 4.
// ---------------------------------------------------------------------------
#define GT_STAGE 32768
#define GT_SMEM  (2 * GT_STAGE)
#define NCHUNK   10

__global__ __launch_bounds__(256, 2) void gemm_mma()
{
    extern __shared__ char sm[];
    const uint32_t smb = smem_to_u32(sm);
    const int tid = threadIdx.x, wid = tid >> 5, lane = tid & 31;

    const int ntile = blockIdx.x & 15;
    const int mtile = (blockIdx.x >> 4) & 127;
    const int dir   = blockIdx.x >> 11;
    const int m0 = mtile * 128, n0 = ntile * 128;

    const int mwarp = (wid >> 2) * 64;
    const int nwarp = (wid & 3) * 32;

    const int crow = tid >> 3;
    const int cc   = tid & 7;
    const int ksub = (cc & 3) * 8;

    const int a_row = (lane & 7) + ((lane >> 3) & 1) * 8;
    const int a_cad = (lane >> 4) & 1;
    const int b_row = (lane & 7) + ((lane >> 4) & 1) * 8;
    const int b_cad = (lane >> 3) & 1;

    float c[4][4][4];
    #pragma unroll
    for (int i = 0; i < 4; i++)
        #pragma unroll
        for (int j = 0; j < 4; j++)
            #pragma unroll
            for (int e = 0; e < 4; e++) c[i][j][e] = 0.f;

    // hi planes only: threads with cc<4 copy 16B each into the low 64B of
    // each 128B row; the upper 64B (old lo-plane slots) are never read.
    #define ISSUE_COPY(kc, stage) do {                                         \
        uint32_t sA = smb + (stage) * GT_STAGE;                                \
        uint32_t sB = sA + 16384;                                              \
        if (cc < 4) {                                                          \
            _Pragma("unroll")                                                  \
            for (int q = 0; q < 4; q++) {                                      \
                int row = crow + q * 32;                                       \
                uint32_t dof = (uint32_t)row * 128 + ((cc ^ (row & 7)) * 16);  \
                const __nv_bfloat16* sa = g_Ahi +                              \
                    (size_t)(m0 + row) * KPAD + (kc) * 32 + ksub;              \
                const __nv_bfloat16* sb = g_Bhi +                              \
                    (size_t)(dir * G4 + n0 + row) * KPAD + (kc) * 32 + ksub;   \
                CP_ASYNC16(sA + dof, sa);                                      \
                CP_ASYNC16(sB + dof, sb);                                      \
            }                                                                  \
        }                                                                      \
        CP_COMMIT();                                                           \
    } while (0)

    ISSUE_COPY(0, 0);

    #pragma unroll 1
    for (int kc = 0; kc < NCHUNK; kc++) {
        if (kc + 1 < NCHUNK) {
            ISSUE_COPY(kc + 1, (kc + 1) & 1);
            CP_WAIT1();
        } else {
            CP_WAIT0();
        }
        __syncthreads();

        const uint32_t sA = smb + (kc & 1) * GT_STAGE;
        const uint32_t sB = sA + 16384;

        #pragma unroll
        for (int ks = 0; ks < 2; ks++) {
            uint32_t ah[4][4], bh[4][2];
            #pragma unroll
            for (int mt = 0; mt < 4; mt++) {
                int row = mwarp + mt * 16 + a_row;
                int swzr = row & 7;
                uint32_t oh = sA + (uint32_t)row * 128 +
                              (((ks * 2 + a_cad) ^ swzr) * 16);
                LDSM_X4(ah[mt][0], ah[mt][1], ah[mt][2], ah[mt][3], oh);
            }
            #pragma unroll
            for (int j = 0; j < 2; j++) {
                int row = nwarp + j * 16 + b_row;
                int swzr = row & 7;
                uint32_t oh = sB + (uint32_t)row * 128 +
                              (((ks * 2 + b_cad) ^ swzr) * 16);
                LDSM_X4(bh[2*j][0], bh[2*j][1], bh[2*j+1][0], bh[2*j+1][1], oh);
            }
            #pragma unroll
            for (int mt = 0; mt < 4; mt++)
                #pragma unroll
                for (int nt = 0; nt < 4; nt++)
                    MMA_BF16(c[mt][nt], ah[mt], bh[nt]);
        }
        __syncthreads();
    }

    const int qrow = lane >> 2;
    const int qcol = (lane & 3) * 2;
    #pragma unroll
    for (int nt = 0; nt < 4; nt++) {
        int coll = nwarp + nt * 8 + qcol;
        int col  = n0 + coll;
        float2 bv = *(const float2*)&g_biasp[dir * G4 + col];
        #pragma unroll
        for (int mt = 0; mt < 4; mt++) {
            #pragma unroll
            for (int half = 0; half < 2; half++) {
                int g = m0 + mwarp + mt * 16 + qrow + half * 8;
                int t = g >> 6, b = g & 63;
                int tout = dir ? (TLEN - 1 - t) : t;
                float2 v;
                v.x = c[mt][nt][half * 2 + 0] + bv.x;
                v.y = c[mt][nt][half * 2 + 1] + bv.y;
                *(float2*)&g_xz[dir][tout][b][col] = v;
            }
        }
    }
}

// ---------------------------------------------------------------------------
// Kernel 2: persistent bidirectional LSTM recurrence — UNCHANGED from R13
// (verified 1330us): pure bf16 recurrence, single-round 4-buffer reduction,
// paired gate stage, release/acquire barrier.
// ---------------------------------------------------------------------------
#define LS_A     0                   // A hi plane: 64KB (rows b, 1KB each)
#define LS_B     65536               // B hi plane: 32KB (rows n, 1KB each)
#define LS_SPILL 98304               // 4 bufs x [64][34] fp32 = 4 x 8704
#define LSTM_SMEM_BYTES (98304 + 4 * 8704)   // 133120

__global__ __launch_bounds__(256, 1) void lstm_kernel()
{
    extern __shared__ char sm[];
    const uint32_t smb = smem_to_u32(sm);
    float* spill = (float*)(sm + LS_SPILL);

    const int tid   = threadIdx.x;
    const int wid   = tid >> 5, lane = tid & 31;
    const int dir   = blockIdx.x >> 6;
    const int slice = blockIdx.x & 63;

    const int mhalf = wid & 1;        // M half: rows mhalf*32..+31
    const int kq    = wid >> 1;       // K quarter: k kq*128..+127

    // ---- one-time: load Wh^T slice (hi plane) into smem ----
    #pragma unroll
    for (int i = tid; i < 2048; i += 256) {       // 2048 16B chunks
        int row = (i >> 6) & 31;
        int c16 = i & 63;
        const __nv_bfloat16* src = &g_WhT[dir][0][slice * 32 + row][c16 * 8];
        uint32_t dst = smb + LS_B + row * 1024 + swz16(c16, row) * 16;
        CP_ASYNC16(dst, src);
    }
    CP_COMMIT();
    CP_WAIT0();
    __syncthreads();

    // ldmatrix lane geometry (verified)
    const int a_row = (lane & 7) + ((lane >> 3) & 1) * 8;
    const int a_cad = (lane >> 4) & 1;
    const int b_row = (lane & 7) + ((lane >> 4) & 1) * 8;
    const int b_cad = (lane >> 3) & 1;
    const int qrow  = lane >> 2;
    const int qcol  = (lane & 3) * 2;
    const unsigned nb = gridDim.x;

    // gate-stage mapping: thread -> (gb, grp) covering units grp, grp+1
    const int gb  = tid >> 2;
    const int grp = (tid & 3) * 2;
    float cell[2] = {0.f, 0.f};       // register cell state for the 2 units

    for (int s = 0; s < TLEN; s++) {
        // ---- stage this warp's A slice: hi plane only (16 chunks/thread) ----
        if (s > 0) {
            const __nv_bfloat16* hb = &g_hb[dir][s & 1][0][0][0];
            #pragma unroll
            for (int q = 0; q < 16; q++) {
                int i = lane + q * 32;
                int rloc  = (i >> 4) & 31;
                int ccc   = i & 15;
                int row   = mhalf * 32 + rloc;
                int gc16  = kq * 16 + ccc;
                const __nv_bfloat16* src = hb + (size_t)row * HIDN + gc16 * 8;
                uint32_t dst = smb + LS_A + row * 1024 + swz16(gc16, row) * 16;
                CP_ASYNC16(dst, src);
            }
            CP_COMMIT();
        }

        // ---- init accumulators from precomputed input projection ----
        float c[2][4][4];
        if (kq == 0) {
            #pragma unroll
            for (int mt = 0; mt < 2; mt++)
                #pragma unroll
                for (int half = 0; half < 2; half++) {
                    int b = mhalf * 32 + mt * 16 + qrow + half * 8;
                    const float* xzp = &g_xz[dir][s][b][slice * 32];
                    #pragma unroll
                    for (int nt = 0; nt < 4; nt++) {
                        float2 v = *(const float2*)&xzp[nt * 8 + qcol];
                        c[mt][nt][half * 2 + 0] = v.x;
                        c[mt][nt][half * 2 + 1] = v.y;
                    }
                }
        } else {
            #pragma unroll
            for (int mt = 0; mt < 2; mt++)
                #pragma unroll
                for (int nt = 0; nt < 4; nt++)
                    #pragma unroll
                    for (int e = 0; e < 4; e++) c[mt][nt][e] = 0.f;
        }

        // ---- MMA: pure bf16, single wait ----
        if (s > 0) {
            CP_WAIT0();
            #pragma unroll 2
            for (int j = 0; j < 8; j++) {
                int gc = kq * 16 + j * 2;
                uint32_t ah[2][4], bh[4][2];
                #pragma unroll
                for (int mt = 0; mt < 2; mt++) {
                    int row = mhalf * 32 + mt * 16 + a_row;
                    uint32_t oh = smb + LS_A + row * 1024 + swz16(gc + a_cad, row) * 16;
                    LDSM_X4(ah[mt][0], ah[mt][1], ah[mt][2], ah[mt][3], oh);
                }
                #pragma unroll
                for (int jn = 0; jn < 2; jn++) {
                    int row = jn * 16 + b_row;
                    uint32_t oh = smb + LS_B + row * 1024 + swz16(gc + b_cad, row) * 16;
                    LDSM_X4(bh[2*jn][0], bh[2*jn][1], bh[2*jn+1][0], bh[2*jn+1][1], oh);
                }
                #pragma unroll
                for (int mt = 0; mt < 2; mt++)
                    #pragma unroll
                    for (int nt = 0; nt < 4; nt++)
                        MMA_BF16(c[mt][nt], ah[mt], bh[nt]);
            }
        }

        // ---- single-round: every warp stores partials to its kq buffer ----
        __syncthreads();
        {
            float* bp = spill + kq * 2176;   // [64][34]
            #pragma unroll
            for (int mt = 0; mt < 2; mt++)
                #pragma unroll
                for (int half = 0; half < 2; half++) {
                    int r = mhalf * 32 + mt * 16 + qrow + half * 8;
                    #pragma unroll
                    for (int nt = 0; nt < 4; nt++) {
                        float2 v;
                        v.x = c[mt][nt][half * 2 + 0];
                        v.y = c[mt][nt][half * 2 + 1];
                        *(float2*)&bp[r * 34 + nt * 8 + qcol] = v;
                    }
                }
        }
        __syncthreads();

        // ---- gates: 256 threads x 2 adjacent units, float2 reads ----
        {
            float2 z2[4];
            #pragma unroll
            for (int g = 0; g < 4; g++) {
                int off = gb * 34 + g * 8 + grp;
                float2 a0 = *(const float2*)&spill[off];
                float2 a1 = *(const float2*)&spill[2176 + off];
                float2 a2 = *(const float2*)&spill[4352 + off];
                float2 a3 = *(const float2*)&spill[6528 + off];
                z2[g].x = (a0.x + a1.x) + (a2.x + a3.x);
                z2[g].y = (a0.y + a1.y) + (a2.y + a3.y);
            }
            float hh[2];
            #pragma unroll
            for (int u = 0; u < 2; u++) {
                float zi = u ? z2[0].y : z2[0].x;
                float zf = u ? z2[1].y : z2[1].x;
                float zg = u ? z2[2].y : z2[2].x;
                float zo = u ? z2[3].y : z2[3].x;
                float gi = fsig(zi);
                float gf = fsig(zf);
                float gg = fmaxf(zg, 0.f);
                float go = fsig(zo);
                float cv = gf * cell[u] + gi * gg;
                cell[u] = cv;
                hh[u] = go * fmaxf(cv, 0.f);
            }
            __nv_bfloat162 vhi;
            vhi.x = __float2bfloat16(hh[0]);
            vhi.y = __float2bfloat16(hh[1]);
            int kk = slice * 8 + grp;
            int pp = (s + 1) & 1;
            *(__nv_bfloat162*)&g_hb[dir][pp][0][gb][kk] = vhi;
            if (s == TLEN - 1) {
                float2 vf; vf.x = hh[0]; vf.y = hh[1];
                *(float2*)&g_h[dir][0][gb][kk] = vf;
            }
        }

        if (s < TLEN - 1) {
            // release/acquire grid barrier (no L1-flushing threadfence)
            __syncthreads();
            if (tid == 0) {
                asm volatile("red.release.gpu.global.add.u32 [%0], %1;"
                             :: "l"(&g_bar), "r"(1u) : "memory");
                unsigned target = (unsigned)(s + 1) * nb;
                unsigned v;
                do {
                    asm volatile("ld.acquire.gpu.global.u32 %0, [%1];"
                                 : "=r"(v) : "l"(&g_bar) : "memory");
                } while (v < target);
            }
            __syncthreads();
        }
    }
}

// ---------------------------------------------------------------------------
// Kernel 3: dense + softmax
// ---------------------------------------------------------------------------
__global__ __launch_bounds__(320) void dense_kernel(
    const float* __restrict__ Wd, const float* __restrict__ bd,
    float* __restrict__ out)
{
    const int b = blockIdx.x;
    const int w = threadIdx.x >> 5, lane = threadIdx.x & 31;
    __shared__ float logits[NCLSN];

    float sum = 0.f;
    for (int k = lane; k < 2 * HIDN; k += 32) {
        float hv = (k < HIDN) ? g_h[0][0][b][k] : g_h[1][0][b][k - HIDN];
        sum = fmaf(hv, Wd[k * NCLSN + w], sum);
    }
    #pragma unroll
    for (int off = 16; off > 0; off >>= 1)
        sum += __shfl_down_sync(0xffffffffu, sum, off);
    if (lane == 0) logits[w] = sum + bd[w];
    __syncthreads();

    if (threadIdx.x == 0) {
        float mx = logits[0];
        #pragma unroll
        for (int n = 1; n < NCLSN; n++) mx = fmaxf(mx, logits[n]);
        float es[NCLSN], ssum = 0.f;
        #pragma unroll
        for (int n = 0; n < NCLSN; n++) { es[n] = expf(logits[n] - mx); ssum += es[n]; }
        float inv = 1.f / ssum;
        #pragma unroll
        for (int n = 0; n < NCLSN; n++) out[b * NCLSN + n] = es[n] * inv;
    }
}

// ---------------------------------------------------------------------------
extern "C" void kernel_launch(void* const* d_in, const int* in_sizes, int n_in,
                              void* d_out, int out_size)
{
    const int*   x    = (const int*)  d_in[0];
    const float* emb  = (const float*)d_in[1];
    const float* Wx_f = (const float*)d_in[2];
    const float* Wh_f = (const float*)d_in[3];
    const float* b_f  = (const float*)d_in[4];
    const float* Wx_b = (const float*)d_in[5];
    const float* Wh_b = (const float*)d_in[6];
    const float* b_b  = (const float*)d_in[7];
    const float* Wd   = (const float*)d_in[8];
    const float* bd   = (const float*)d_in[9];
    float* out = (float*)d_out;

    (void)in_sizes; (void)n_in; (void)out_size;

    cudaFuncSetAttribute(gemm_mma,
                         cudaFuncAttributeMaxDynamicSharedMemorySize, GT_SMEM);
    cudaFuncSetAttribute(lstm_kernel,
                         cudaFuncAttributeMaxDynamicSharedMemorySize, LSTM_SMEM_BYTES);

    prep_w<<<dim3(G4, 2), KPAD>>>(Wx_f, b_f, Wx_b, b_b);
    prep_wh<<<dim3(G4, 2), HIDN>>>(Wh_f, Wh_b);
    prep_a<<<MROWS, KPAD>>>(x, emb);
    gemm_mma<<<2 * 128 * 16, 256, GT_SMEM>>>();
    lstm_kernel<<<128, 256, LSTM_SMEM_BYTES>>>();
    dense_kernel<<<BATCHN, 320>>>(Wd, bd, out);
}

// round 15
// speedup vs baseline: 1.7194x; 1.2167x over previous
#include <cuda_runtime.h>
#include <cuda_bf16.h>
#include <math.h>
#include <stdint.h>

#define VOCABN 50000
#define EMBN   300
#define KPAD   320     // EMB padded to 10 chunks of 32
#define TLEN   256
#define HIDN   512
#define G4     2048    // 4*HID
#define NCLSN  10
#define BATCHN 64
#define MROWS  (TLEN*BATCHN)

// ---------------------------------------------------------------------------
// Device scratch
// ---------------------------------------------------------------------------
__device__ __align__(256) float g_xz[2][TLEN][BATCHN][G4]; // permuted gate cols
__device__ __align__(256) float g_h[2][2][BATCHN][HIDN];   // fp32 h (final step, for dense)
__device__ unsigned g_bar;                                 // grid barrier counter

__device__ __align__(256) __nv_bfloat16 g_Ahi[(size_t)MROWS * KPAD];
__device__ __align__(256) __nv_bfloat16 g_Bhi[(size_t)2 * G4 * KPAD];
__device__ __align__(256) float g_biasp[2 * G4];

// recurrence operands: h and Wh^T as bf16 (hi plane only)
__device__ __align__(256) __nv_bfloat16 g_hb[2][2][2][BATCHN][HIDN];   // [dir][pp][plane][b][k]
__device__ __align__(256) __nv_bfloat16 g_WhT[2][2][G4][HIDN];         // [dir][plane][p][k]

__device__ __forceinline__ int perm_src(int p) {
    return ((p >> 3) & 3) * HIDN + (p >> 5) * 8 + (p & 7);
}

__device__ __forceinline__ uint32_t smem_to_u32(const void* p) {
    uint32_t a;
    asm("{ .reg .u64 t; cvta.to.shared.u64 t, %1; cvt.u32.u64 %0, t; }"
        : "=r"(a) : "l"(p));
    return a;
}

// ---------------------------------------------------------------------------
// mma.sync / ldmatrix / cp.async helpers (baseline PTX, no 'a' features)
// ---------------------------------------------------------------------------
#define LDSM_X4(r0, r1, r2, r3, addr) \
    asm volatile("ldmatrix.sync.aligned.m8n8.x4.shared.b16 {%0,%1,%2,%3}, [%4];" \
        : "=r"(r0), "=r"(r1), "=r"(r2), "=r"(r3) : "r"(addr))

#define MMA_BF16(c, a, b) \
    asm volatile("mma.sync.aligned.m16n8k16.row.col.f32.bf16.bf16.f32 " \
        "{%0,%1,%2,%3}, {%4,%5,%6,%7}, {%8,%9}, {%0,%1,%2,%3};" \
        : "+f"((c)[0]), "+f"((c)[1]), "+f"((c)[2]), "+f"((c)[3]) \
        : "r"((a)[0]), "r"((a)[1]), "r"((a)[2]), "r"((a)[3]), \
          "r"((b)[0]), "r"((b)[1]))

#define CP_ASYNC16(dst, src) \
    asm volatile("cp.async.cg.shared.global [%0], [%1], 16;" \
        :: "r"(dst), "l"(src) : "memory")
#define CP_COMMIT() asm volatile("cp.async.commit_group;" ::: "memory")
#define CP_WAIT1()  asm volatile("cp.async.wait_group 1;" ::: "memory")
#define CP_WAIT0()  asm volatile("cp.async.wait_group 0;" ::: "memory")

#define BAR_SYNC(id, n) \
    asm volatile("bar.sync %0, %1;" :: "r"(id), "r"(n) : "memory")

// swizzle of a 16B-chunk index within a 1KB row (XOR low 3 bits with row&7)
__device__ __forceinline__ uint32_t swz16(uint32_t c16, uint32_t row) {
    return (c16 & ~7u) | ((c16 ^ row) & 7u);
}

__device__ __forceinline__ float fsig(float x) {
    return __fdividef(1.f, 1.f + __expf(-x));
}

// ---------------------------------------------------------------------------
// Prep kernels (bf16 round-to-nearest)
// ---------------------------------------------------------------------------
__global__ __launch_bounds__(KPAD) void prep_w(
    const float* __restrict__ Wx_f, const float* __restrict__ b_f,
    const float* __restrict__ Wx_b, const float* __restrict__ b_b)
{
    int n = blockIdx.x, dir = blockIdx.y, k = threadIdx.x;
    if (n == 0 && dir == 0 && k == 0) g_bar = 0u;     // grid-barrier reset
    int src = perm_src(n);
    const float* Wx = dir ? Wx_b : Wx_f;
    float v = (k < EMBN) ? Wx[(size_t)k * G4 + src] : 0.f;
    g_Bhi[(size_t)(dir * G4 + n) * KPAD + k] = __float2bfloat16(v);
    if (k == 0) g_biasp[dir * G4 + n] = (dir ? b_b : b_f)[src];
}

__global__ __launch_bounds__(KPAD) void prep_a(
    const int* __restrict__ x, const float* __restrict__ emb)
{
    int row = blockIdx.x;
    int t = row >> 6, b = row & 63;
    __shared__ int tok;
    if (threadIdx.x == 0) tok = x[b * TLEN + t];
    __syncthreads();
    int k = threadIdx.x;
    float v = (k < EMBN) ? emb[(size_t)tok * EMBN + k] : 0.f;
    g_Ahi[(size_t)row * KPAD + k] = __float2bfloat16(v);
}

__global__ __launch_bounds__(HIDN) void prep_wh(
    const float* __restrict__ Wh_f, const float* __restrict__ Wh_b)
{
    int p = blockIdx.x, dir = blockIdx.y, k = threadIdx.x;
    int src = perm_src(p);
    float v = (dir ? Wh_b : Wh_f)[(size_t)k * G4 + src];
    g_WhT[dir][0][p][k] = __float2bfloat16(v);
}

// ---------------------------------------------------------------------------
// Tensor-core input projection — pure bf16 (unchanged from R14, 143us)
// ---------------------------------------------------------------------------
#define GT_STAGE 32768
#define GT_SMEM  (2 * GT_STAGE)
#define NCHUNK   10

__global__ __launch_bounds__(256, 2) void gemm_mma()
{
    extern __shared__ char sm[];
    const uint32_t smb = smem_to_u32(sm);
    const int tid = threadIdx.x, wid = tid >> 5, lane = tid & 31;

    const int ntile = blockIdx.x & 15;
    const int mtile = (blockIdx.x >> 4) & 127;
    const int dir   = blockIdx.x >> 11;
    const int m0 = mtile * 128, n0 = ntile * 128;

    const int mwarp = (wid >> 2) * 64;
    const int nwarp = (wid & 3) * 32;

    const int crow = tid >> 3;
    const int cc   = tid & 7;
    const int ksub = (cc & 3) * 8;

    const int a_row = (lane & 7) + ((lane >> 3) & 1) * 8;
    const int a_cad = (lane >> 4) & 1;
    const int b_row = (lane & 7) + ((lane >> 4) & 1) * 8;
    const int b_cad = (lane >> 3) & 1;

    float c[4][4][4];
    #pragma unroll
    for (int i = 0; i < 4; i++)
        #pragma unroll
        for (int j = 0; j < 4; j++)
            #pragma unroll
            for (int e = 0; e < 4; e++) c[i][j][e] = 0.f;

    #define ISSUE_COPY(kc, stage) do {                                         \
        uint32_t sA = smb + (stage) * GT_STAGE;                                \
        uint32_t sB = sA + 16384;                                              \
        if (cc < 4) {                                                          \
            _Pragma("unroll")                                                  \
            for (int q = 0; q < 4; q++) {                                      \
                int row = crow + q * 32;                                       \
                uint32_t dof = (uint32_t)row * 128 + ((cc ^ (row & 7)) * 16);  \
                const __nv_bfloat16* sa = g_Ahi +                              \
                    (size_t)(m0 + row) * KPAD + (kc) * 32 + ksub;              \
                const __nv_bfloat16* sb = g_Bhi +                              \
                    (size_t)(dir * G4 + n0 + row) * KPAD + (kc) * 32 + ksub;   \
                CP_ASYNC16(sA + dof, sa);                                      \
                CP_ASYNC16(sB + dof, sb);                                      \
            }                                                                  \
        }                                                                      \
        CP_COMMIT();                                                           \
    } while (0)

    ISSUE_COPY(0, 0);

    #pragma unroll 1
    for (int kc = 0; kc < NCHUNK; kc++) {
        if (kc + 1 < NCHUNK) {
            ISSUE_COPY(kc + 1, (kc + 1) & 1);
            CP_WAIT1();
        } else {
            CP_WAIT0();
        }
        __syncthreads();

        const uint32_t sA = smb + (kc & 1) * GT_STAGE;
        const uint32_t sB = sA + 16384;

        #pragma unroll
        for (int ks = 0; ks < 2; ks++) {
            uint32_t ah[4][4], bh[4][2];
            #pragma unroll
            for (int mt = 0; mt < 4; mt++) {
                int row = mwarp + mt * 16 + a_row;
                int swzr = row & 7;
                uint32_t oh = sA + (uint32_t)row * 128 +
                              (((ks * 2 + a_cad) ^ swzr) * 16);
                LDSM_X4(ah[mt][0], ah[mt][1], ah[mt][2], ah[mt][3], oh);
            }
            #pragma unroll
            for (int j = 0; j < 2; j++) {
                int row = nwarp + j * 16 + b_row;
                int swzr = row & 7;
                uint32_t oh = sB + (uint32_t)row * 128 +
                              (((ks * 2 + b_cad) ^ swzr) * 16);
                LDSM_X4(bh[2*j][0], bh[2*j][1], bh[2*j+1][0], bh[2*j+1][1], oh);
            }
            #pragma unroll
            for (int mt = 0; mt < 4; mt++)
                #pragma unroll
                for (int nt = 0; nt < 4; nt++)
                    MMA_BF16(c[mt][nt], ah[mt], bh[nt]);
        }
        __syncthreads();
    }

    const int qrow = lane >> 2;
    const int qcol = (lane & 3) * 2;
    #pragma unroll
    for (int nt = 0; nt < 4; nt++) {
        int coll = nwarp + nt * 8 + qcol;
        int col  = n0 + coll;
        float2 bv = *(const float2*)&g_biasp[dir * G4 + col];
        #pragma unroll
        for (int mt = 0; mt < 4; mt++) {
            #pragma unroll
            for (int half = 0; half < 2; half++) {
                int g = m0 + mwarp + mt * 16 + qrow + half * 8;
                int t = g >> 6, b = g & 63;
                int tout = dir ? (TLEN - 1 - t) : t;
                float2 v;
                v.x = c[mt][nt][half * 2 + 0] + bv.x;
                v.y = c[mt][nt][half * 2 + 1] + bv.y;
                *(float2*)&g_xz[dir][tout][b][col] = v;
            }
        }
    }
}

// ---------------------------------------------------------------------------
// Kernel 2: persistent bidirectional LSTM recurrence, WARP-SPECIALIZED.
// NEW vs R14 (verified 1173us):
//  - consumers (warps 0-3): warp w owns M rows w*16..+15 x FULL K=512.
//    No cross-warp K reduction, no spill smem. Gates + cell state fully
//    in registers (fragment col nt = gate index under the permuted layout).
//  - producers (warps 4-7): poll grid barrier + stage h hi plane (64KB)
//    via cp.async while consumers run the previous step's gate math.
//    Handoff = one __syncthreads per step.
//  - consumer-only named barrier + leader release-arrive for the grid barrier.
// ---------------------------------------------------------------------------
#define LS_A     0                   // h hi plane: 64KB (rows b, 1KB each)
#define LS_B     65536               // Wh hi plane: 32KB (rows n, 1KB each)
#define LSTM_SMEM_BYTES 98304

__global__ __launch_bounds__(256, 1) void lstm_kernel()
{
    extern __shared__ char sm[];
    const uint32_t smb = smem_to_u32(sm);

    const int tid   = threadIdx.x;
    const int wid   = tid >> 5, lane = tid & 31;
    const int dir   = blockIdx.x >> 6;
    const int slice = blockIdx.x & 63;

    // ---- one-time: load Wh^T slice (hi plane) into smem (all warps) ----
    #pragma unroll
    for (int i = tid; i < 2048; i += 256) {
        int row = (i >> 6) & 31;
        int c16 = i & 63;
        const __nv_bfloat16* src = &g_WhT[dir][0][slice * 32 + row][c16 * 8];
        uint32_t dst = smb + LS_B + row * 1024 + swz16(c16, row) * 16;
        CP_ASYNC16(dst, src);
    }
    CP_COMMIT();
    CP_WAIT0();
    __syncthreads();

    const int a_row = (lane & 7) + ((lane >> 3) & 1) * 8;
    const int a_cad = (lane >> 4) & 1;
    const int b_row = (lane & 7) + ((lane >> 4) & 1) * 8;
    const int b_cad = (lane >> 3) & 1;
    const int qrow  = lane >> 2;
    const int qcol  = (lane & 3) * 2;
    const unsigned nb = gridDim.x;

    const int mrow = wid * 16;        // consumer M base (wid<4)
    const int pw   = wid - 4;         // producer index (wid>=4)

    float cell[2][2];                  // [half][u] register cell state
    cell[0][0] = cell[0][1] = cell[1][0] = cell[1][1] = 0.f;

    for (int s = 0; s < TLEN; s++) {
        // ---- producers: wait for all CTAs' h(s-1), then stage it ----
        if (wid >= 4 && s > 0) {
            if (tid == 128) {
                unsigned target = (unsigned)s * nb;
                unsigned v;
                do {
                    asm volatile("ld.acquire.gpu.global.u32 %0, [%1];"
                                 : "=r"(v) : "l"(&g_bar) : "memory");
                } while (v < target);
            }
            BAR_SYNC(2, 128);          // producer group
            const __nv_bfloat16* hb = &g_hb[dir][s & 1][0][0][0];
            #pragma unroll
            for (int q = 0; q < 32; q++) {
                int i   = lane + q * 32;           // 0..1023
                int row = pw * 16 + (i >> 6);      // 16 rows per producer warp
                int c16 = i & 63;
                const __nv_bfloat16* src = hb + (size_t)row * HIDN + c16 * 8;
                uint32_t dst = smb + LS_A + row * 1024 + swz16(c16, row) * 16;
                CP_ASYNC16(dst, src);
            }
            CP_COMMIT();
            CP_WAIT0();
        }

        // ---- consumers: prefetch xz(s) while producers stage ----
        float pre[4][4];
        if (wid < 4) {
            #pragma unroll
            for (int half = 0; half < 2; half++) {
                int b = mrow + qrow + half * 8;
                const float* xzp = &g_xz[dir][s][b][slice * 32];
                #pragma unroll
                for (int nt = 0; nt < 4; nt++) {
                    float2 v = *(const float2*)&xzp[nt * 8 + qcol];
                    pre[nt][half * 2 + 0] = v.x;
                    pre[nt][half * 2 + 1] = v.y;
                }
            }
        }

        __syncthreads();   // handoff: staged h(s-1) visible to consumers

        if (wid < 4) {
            float c[4][4];
            #pragma unroll
            for (int nt = 0; nt < 4; nt++)
                #pragma unroll
                for (int e = 0; e < 4; e++) c[nt][e] = pre[nt][e];

            if (s > 0) {
                #pragma unroll 4
                for (int j = 0; j < 32; j++) {
                    uint32_t ah[4], bh[4][2];
                    {
                        int row = mrow + a_row;
                        uint32_t oh = smb + LS_A + row * 1024 +
                                      swz16(2 * j + a_cad, row) * 16;
                        LDSM_X4(ah[0], ah[1], ah[2], ah[3], oh);
                    }
                    #pragma unroll
                    for (int jn = 0; jn < 2; jn++) {
                        int row = jn * 16 + b_row;
                        uint32_t oh = smb + LS_B + row * 1024 +
                                      swz16(2 * j + b_cad, row) * 16;
                        LDSM_X4(bh[2*jn][0], bh[2*jn][1],
                                bh[2*jn+1][0], bh[2*jn+1][1], oh);
                    }
                    #pragma unroll
                    for (int nt = 0; nt < 4; nt++)
                        MMA_BF16(c[nt], ah, bh[nt]);
                }
            }

            // ---- gates fully in registers (nt = gate index i,f,g,o) ----
            const int pp = (s + 1) & 1;
            #pragma unroll
            for (int half = 0; half < 2; half++) {
                int b = mrow + qrow + half * 8;
                float hh[2];
                #pragma unroll
                for (int u = 0; u < 2; u++) {
                    int e = half * 2 + u;
                    float gi = fsig(c[0][e]);
                    float gf = fsig(c[1][e]);
                    float gg = fmaxf(c[2][e], 0.f);
                    float go = fsig(c[3][e]);
                    float cv = gf * cell[half][u] + gi * gg;
                    cell[half][u] = cv;
                    hh[u] = go * fmaxf(cv, 0.f);
                }
                __nv_bfloat162 vh;
                vh.x = __float2bfloat16(hh[0]);
                vh.y = __float2bfloat16(hh[1]);
                int kk = slice * 8 + qcol;
                *(__nv_bfloat162*)&g_hb[dir][pp][0][b][kk] = vh;
                if (s == TLEN - 1) {
                    float2 vf; vf.x = hh[0]; vf.y = hh[1];
                    *(float2*)&g_h[dir][0][b][kk] = vf;
                }
            }

            if (s < TLEN - 1) {
                BAR_SYNC(1, 128);      // consumer group: h stores done
                if (tid == 0) {
                    asm volatile("red.release.gpu.global.add.u32 [%0], %1;"
                                 :: "l"(&g_bar), "r"(1u) : "memory");
                }
            }
        }
    }
}

// ---------------------------------------------------------------------------
// Kernel 3: dense + softmax
// ---------------------------------------------------------------------------
__global__ __launch_bounds__(320) void dense_kernel(
    const float* __restrict__ Wd, const float* __restrict__ bd,
    float* __restrict__ out)
{
    const int b = blockIdx.x;
    const int w = threadIdx.x >> 5, lane = threadIdx.x & 31;
    __shared__ float logits[NCLSN];

    float sum = 0.f;
    for (int k = lane; k < 2 * HIDN; k += 32) {
        float hv = (k < HIDN) ? g_h[0][0][b][k] : g_h[1][0][b][k - HIDN];
        sum = fmaf(hv, Wd[k * NCLSN + w], sum);
    }
    #pragma unroll
    for (int off = 16; off > 0; off >>= 1)
        sum += __shfl_down_sync(0xffffffffu, sum, off);
    if (lane == 0) logits[w] = sum + bd[w];
    __syncthreads();

    if (threadIdx.x == 0) {
        float mx = logits[0];
        #pragma unroll
        for (int n = 1; n < NCLSN; n++) mx = fmaxf(mx, logits[n]);
        float es[NCLSN], ssum = 0.f;
        #pragma unroll
        for (int n = 0; n < NCLSN; n++) { es[n] = expf(logits[n] - mx); ssum += es[n]; }
        float inv = 1.f / ssum;
        #pragma unroll
        for (int n = 0; n < NCLSN; n++) out[b * NCLSN + n] = es[n] * inv;
    }
}

// ---------------------------------------------------------------------------
extern "C" void kernel_launch(void* const* d_in, const int* in_sizes, int n_in,
                              void* d_out, int out_size)
{
    const int*   x    = (const int*)  d_in[0];
    const float* emb  = (const float*)d_in[1];
    const float* Wx_f = (const float*)d_in[2];
    const float* Wh_f = (const float*)d_in[3];
    const float* b_f  = (const float*)d_in[4];
    const float* Wx_b = (const float*)d_in[5];
    const float* Wh_b = (const float*)d_in[6];
    const float* b_b  = (const float*)d_in[7];
    const float* Wd   = (const float*)d_in[8];
    const float* bd   = (const float*)d_in[9];
    float* out = (float*)d_out;

    (void)in_sizes; (void)n_in; (void)out_size;

    cudaFuncSetAttribute(gemm_mma,
                         cudaFuncAttributeMaxDynamicSharedMemorySize, GT_SMEM);
    cudaFuncSetAttribute(lstm_kernel,
                         cudaFuncAttributeMaxDynamicSharedMemorySize, LSTM_SMEM_BYTES);

    prep_w<<<dim3(G4, 2), KPAD>>>(Wx_f, b_f, Wx_b, b_b);
    prep_wh<<<dim3(G4, 2), HIDN>>>(Wh_f, Wh_b);
    prep_a<<<MROWS, KPAD>>>(x, emb);
    gemm_mma<<<2 * 128 * 16, 256, GT_SMEM>>>();
    lstm_kernel<<<128, 256, LSTM_SMEM_BYTES>>>();
    dense_kernel<<<BATCHN, 320>>>(Wd, bd, out);
}

// round 16
// speedup vs baseline: 1.7899x; 1.0410x over previous
#include <cuda_runtime.h>
#include <cuda_bf16.h>
#include <math.h>
#include <stdint.h>

#define VOCABN 50000
#define EMBN   300
#define KPAD   320     // EMB padded: 5 chunks of 64
#define TLEN   256
#define HIDN   512
#define G4     2048    // 4*HID
#define NCLSN  10
#define BATCHN 64
#define MROWS  (TLEN*BATCHN)

// ---------------------------------------------------------------------------
// Device scratch
// ---------------------------------------------------------------------------
__device__ __align__(256) float g_xz[2][TLEN][BATCHN][G4]; // permuted gate cols
__device__ __align__(256) float g_h[2][2][BATCHN][HIDN];   // fp32 h (final step, for dense)
__device__ unsigned g_bar;                                 // grid barrier counter

__device__ __align__(256) __nv_bfloat16 g_Ahi[(size_t)MROWS * KPAD];
__device__ __align__(256) __nv_bfloat16 g_Bhi[(size_t)2 * G4 * KPAD];
__device__ __align__(256) float g_biasp[2 * G4];

// recurrence operands: h and Wh^T as bf16 (hi plane only)
__device__ __align__(256) __nv_bfloat16 g_hb[2][2][2][BATCHN][HIDN];   // [dir][pp][plane][b][k]
__device__ __align__(256) __nv_bfloat16 g_WhT[2][2][G4][HIDN];         // [dir][plane][p][k]

__device__ __forceinline__ int perm_src(int p) {
    return ((p >> 3) & 3) * HIDN + (p >> 5) * 8 + (p & 7);
}

__device__ __forceinline__ uint32_t smem_to_u32(const void* p) {
    uint32_t a;
    asm("{ .reg .u64 t; cvta.to.shared.u64 t, %1; cvt.u32.u64 %0, t; }"
        : "=r"(a) : "l"(p));
    return a;
}

// ---------------------------------------------------------------------------
// mma.sync / ldmatrix / cp.async helpers (baseline PTX, no 'a' features)
// ---------------------------------------------------------------------------
#define LDSM_X4(r0, r1, r2, r3, addr) \
    asm volatile("ldmatrix.sync.aligned.m8n8.x4.shared.b16 {%0,%1,%2,%3}, [%4];" \
        : "=r"(r0), "=r"(r1), "=r"(r2), "=r"(r3) : "r"(addr))

#define MMA_BF16(c, a, b) \
    asm volatile("mma.sync.aligned.m16n8k16.row.col.f32.bf16.bf16.f32 " \
        "{%0,%1,%2,%3}, {%4,%5,%6,%7}, {%8,%9}, {%0,%1,%2,%3};" \
        : "+f"((c)[0]), "+f"((c)[1]), "+f"((c)[2]), "+f"((c)[3]) \
        : "r"((a)[0]), "r"((a)[1]), "r"((a)[2]), "r"((a)[3]), \
          "r"((b)[0]), "r"((b)[1]))

#define CP_ASYNC16(dst, src) \
    asm volatile("cp.async.cg.shared.global [%0], [%1], 16;" \
        :: "r"(dst), "l"(src) : "memory")
#define CP_COMMIT() asm volatile("cp.async.commit_group;" ::: "memory")
#define CP_WAIT1()  asm volatile("cp.async.wait_group 1;" ::: "memory")
#define CP_WAIT0()  asm volatile("cp.async.wait_group 0;" ::: "memory")

#define BAR_SYNC(id, n) \
    asm volatile("bar.sync %0, %1;" :: "r"(id), "r"(n) : "memory")

// swizzle of a 16B-chunk index within a 1KB/128B row (XOR low 3 bits, row&7)
__device__ __forceinline__ uint32_t swz16(uint32_t c16, uint32_t row) {
    return (c16 & ~7u) | ((c16 ^ row) & 7u);
}

__device__ __forceinline__ float fsig(float x) {
    return __fdividef(1.f, 1.f + __expf(-x));
}

// ---------------------------------------------------------------------------
// Prep kernels (bf16 round-to-nearest)
// ---------------------------------------------------------------------------
__global__ __launch_bounds__(KPAD) void prep_w(
    const float* __restrict__ Wx_f, const float* __restrict__ b_f,
    const float* __restrict__ Wx_b, const float* __restrict__ b_b)
{
    int n = blockIdx.x, dir = blockIdx.y, k = threadIdx.x;
    if (n == 0 && dir == 0 && k == 0) g_bar = 0u;     // grid-barrier reset
    int src = perm_src(n);
    const float* Wx = dir ? Wx_b : Wx_f;
    float v = (k < EMBN) ? Wx[(size_t)k * G4 + src] : 0.f;
    g_Bhi[(size_t)(dir * G4 + n) * KPAD + k] = __float2bfloat16(v);
    if (k == 0) g_biasp[dir * G4 + n] = (dir ? b_b : b_f)[src];
}

__global__ __launch_bounds__(KPAD) void prep_a(
    const int* __restrict__ x, const float* __restrict__ emb)
{
    int row = blockIdx.x;
    int t = row >> 6, b = row & 63;
    __shared__ int tok;
    if (threadIdx.x == 0) tok = x[b * TLEN + t];
    __syncthreads();
    int k = threadIdx.x;
    float v = (k < EMBN) ? emb[(size_t)tok * EMBN + k] : 0.f;
    g_Ahi[(size_t)row * KPAD + k] = __float2bfloat16(v);
}

__global__ __launch_bounds__(HIDN) void prep_wh(
    const float* __restrict__ Wh_f, const float* __restrict__ Wh_b)
{
    int p = blockIdx.x, dir = blockIdx.y, k = threadIdx.x;
    int src = perm_src(p);
    float v = (dir ? Wh_b : Wh_f)[(size_t)k * G4 + src];
    g_WhT[dir][0][p][k] = __float2bfloat16(v);
}

// ---------------------------------------------------------------------------
// Tensor-core input projection — pure bf16, NOW k64 chunks: full 128B smem
// rows, 5 chunk iterations (was 10), 64 MMAs per iteration, half the syncs.
// ---------------------------------------------------------------------------
#define GT_STAGE 32768     // A 16KB + B 16KB per stage (128 rows x 128B)
#define GT_SMEM  (2 * GT_STAGE)
#define NCHUNK   5

__global__ __launch_bounds__(256, 2) void gemm_mma()
{
    extern __shared__ char sm[];
    const uint32_t smb = smem_to_u32(sm);
    const int tid = threadIdx.x, wid = tid >> 5, lane = tid & 31;

    const int ntile = blockIdx.x & 15;
    const int mtile = (blockIdx.x >> 4) & 127;
    const int dir   = blockIdx.x >> 11;
    const int m0 = mtile * 128, n0 = ntile * 128;

    const int mwarp = (wid >> 2) * 64;
    const int nwarp = (wid & 3) * 32;

    const int crow = tid >> 3;     // 0..31
    const int cc   = tid & 7;      // 16B column 0..7 (full row)

    const int a_row = (lane & 7) + ((lane >> 3) & 1) * 8;
    const int a_cad = (lane >> 4) & 1;
    const int b_row = (lane & 7) + ((lane >> 4) & 1) * 8;
    const int b_cad = (lane >> 3) & 1;

    float c[4][4][4];
    #pragma unroll
    for (int i = 0; i < 4; i++)
        #pragma unroll
        for (int j = 0; j < 4; j++)
            #pragma unroll
            for (int e = 0; e < 4; e++) c[i][j][e] = 0.f;

    #define ISSUE_COPY(kc, stage) do {                                         \
        uint32_t sA = smb + (stage) * GT_STAGE;                                \
        uint32_t sB = sA + 16384;                                              \
        _Pragma("unroll")                                                      \
        for (int q = 0; q < 4; q++) {                                          \
            int row = crow + q * 32;                                           \
            uint32_t dof = (uint32_t)row * 128 + ((cc ^ (row & 7)) * 16);      \
            const __nv_bfloat16* sa = g_Ahi +                                  \
                (size_t)(m0 + row) * KPAD + (kc) * 64 + cc * 8;                \
            const __nv_bfloat16* sb = g_Bhi +                                  \
                (size_t)(dir * G4 + n0 + row) * KPAD + (kc) * 64 + cc * 8;     \
            CP_ASYNC16(sA + dof, sa);                                          \
            CP_ASYNC16(sB + dof, sb);                                          \
        }                                                                      \
        CP_COMMIT();                                                           \
    } while (0)

    ISSUE_COPY(0, 0);

    #pragma unroll 1
    for (int kc = 0; kc < NCHUNK; kc++) {
        if (kc + 1 < NCHUNK) {
            ISSUE_COPY(kc + 1, (kc + 1) & 1);
            CP_WAIT1();
        } else {
            CP_WAIT0();
        }
        __syncthreads();

        const uint32_t sA = smb + (kc & 1) * GT_STAGE;
        const uint32_t sB = sA + 16384;

        #pragma unroll
        for (int ks = 0; ks < 4; ks++) {
            uint32_t ah[4][4], bh[4][2];
            #pragma unroll
            for (int mt = 0; mt < 4; mt++) {
                int row = mwarp + mt * 16 + a_row;
                int swzr = row & 7;
                uint32_t oh = sA + (uint32_t)row * 128 +
                              (((ks * 2 + a_cad) ^ swzr) * 16);
                LDSM_X4(ah[mt][0], ah[mt][1], ah[mt][2], ah[mt][3], oh);
            }
            #pragma unroll
            for (int j = 0; j < 2; j++) {
                int row = nwarp + j * 16 + b_row;
                int swzr = row & 7;
                uint32_t oh = sB + (uint32_t)row * 128 +
                              (((ks * 2 + b_cad) ^ swzr) * 16);
                LDSM_X4(bh[2*j][0], bh[2*j][1], bh[2*j+1][0], bh[2*j+1][1], oh);
            }
            #pragma unroll
            for (int mt = 0; mt < 4; mt++)
                #pragma unroll
                for (int nt = 0; nt < 4; nt++)
                    MMA_BF16(c[mt][nt], ah[mt], bh[nt]);
        }
        __syncthreads();
    }

    const int qrow = lane >> 2;
    const int qcol = (lane & 3) * 2;
    #pragma unroll
    for (int nt = 0; nt < 4; nt++) {
        int coll = nwarp + nt * 8 + qcol;
        int col  = n0 + coll;
        float2 bv = *(const float2*)&g_biasp[dir * G4 + col];
        #pragma unroll
        for (int mt = 0; mt < 4; mt++) {
            #pragma unroll
            for (int half = 0; half < 2; half++) {
                int g = m0 + mwarp + mt * 16 + qrow + half * 8;
                int t = g >> 6, b = g & 63;
                int tout = dir ? (TLEN - 1 - t) : t;
                float2 v;
                v.x = c[mt][nt][half * 2 + 0] + bv.x;
                v.y = c[mt][nt][half * 2 + 1] + bv.y;
                *(float2*)&g_xz[dir][tout][b][col] = v;
            }
        }
    }
}

// ---------------------------------------------------------------------------
// Kernel 2: persistent bidirectional LSTM recurrence, warp-specialized
// (verified 964us). NEW: per-pair handoff — consumer warp w depends only on
// producer w+4's rows, so bar.sync(3+w, 64) replaces the全-CTA syncthreads.
// ---------------------------------------------------------------------------
#define LS_A     0                   // h hi plane: 64KB (rows b, 1KB each)
#define LS_B     65536               // Wh hi plane: 32KB (rows n, 1KB each)
#define LSTM_SMEM_BYTES 98304

__global__ __launch_bounds__(256, 1) void lstm_kernel()
{
    extern __shared__ char sm[];
    const uint32_t smb = smem_to_u32(sm);

    const int tid   = threadIdx.x;
    const int wid   = tid >> 5, lane = tid & 31;
    const int dir   = blockIdx.x >> 6;
    const int slice = blockIdx.x & 63;

    // ---- one-time: load Wh^T slice (hi plane) into smem (all warps) ----
    #pragma unroll
    for (int i = tid; i < 2048; i += 256) {
        int row = (i >> 6) & 31;
        int c16 = i & 63;
        const __nv_bfloat16* src = &g_WhT[dir][0][slice * 32 + row][c16 * 8];
        uint32_t dst = smb + LS_B + row * 1024 + swz16(c16, row) * 16;
        CP_ASYNC16(dst, src);
    }
    CP_COMMIT();
    CP_WAIT0();
    __syncthreads();

    const int a_row = (lane & 7) + ((lane >> 3) & 1) * 8;
    const int a_cad = (lane >> 4) & 1;
    const int b_row = (lane & 7) + ((lane >> 4) & 1) * 8;
    const int b_cad = (lane >> 3) & 1;
    const int qrow  = lane >> 2;
    const int qcol  = (lane & 3) * 2;
    const unsigned nb = gridDim.x;

    const int mrow = (wid & 3) * 16;  // M base for pair (consumer wid<4)
    const int pw   = wid - 4;         // producer index (wid>=4)

    float cell[2][2];
    cell[0][0] = cell[0][1] = cell[1][0] = cell[1][1] = 0.f;

    for (int s = 0; s < TLEN; s++) {
        // ---- producers: wait for all CTAs' h(s-1), then stage own 16 rows ----
        if (wid >= 4 && s > 0) {
            if (tid == 128) {
                unsigned target = (unsigned)s * nb;
                unsigned v;
                do {
                    asm volatile("ld.acquire.gpu.global.u32 %0, [%1];"
                                 : "=r"(v) : "l"(&g_bar) : "memory");
                } while (v < target);
            }
            BAR_SYNC(2, 128);          // producer group: barrier observed
            const __nv_bfloat16* hb = &g_hb[dir][s & 1][0][0][0];
            #pragma unroll
            for (int q = 0; q < 32; q++) {
                int i   = lane + q * 32;           // 0..1023
                int row = pw * 16 + (i >> 6);
                int c16 = i & 63;
                const __nv_bfloat16* src = hb + (size_t)row * HIDN + c16 * 8;
                uint32_t dst = smb + LS_A + row * 1024 + swz16(c16, row) * 16;
                CP_ASYNC16(dst, src);
            }
            CP_COMMIT();
            CP_WAIT0();
            BAR_SYNC(3 + pw, 64);      // hand off to consumer pw
        }

        if (wid < 4) {
            // prefetch xz(s) (overlaps producer staging)
            float c[4][4];
            #pragma unroll
            for (int half = 0; half < 2; half++) {
                int b = mrow + qrow + half * 8;
                const float* xzp = &g_xz[dir][s][b][slice * 32];
                #pragma unroll
                for (int nt = 0; nt < 4; nt++) {
                    float2 v = *(const float2*)&xzp[nt * 8 + qcol];
                    c[nt][half * 2 + 0] = v.x;
                    c[nt][half * 2 + 1] = v.y;
                }
            }

            if (s > 0) {
                BAR_SYNC(3 + wid, 64);  // wait for own producer's rows
                #pragma unroll 4
                for (int j = 0; j < 32; j++) {
                    uint32_t ah[4], bh[4][2];
                    {
                        int row = mrow + a_row;
                        uint32_t oh = smb + LS_A + row * 1024 +
                                      swz16(2 * j + a_cad, row) * 16;
                        LDSM_X4(ah[0], ah[1], ah[2], ah[3], oh);
                    }
                    #pragma unroll
                    for (int jn = 0; jn < 2; jn++) {
                        int row = jn * 16 + b_row;
                        uint32_t oh = smb + LS_B + row * 1024 +
                                      swz16(2 * j + b_cad, row) * 16;
                        LDSM_X4(bh[2*jn][0], bh[2*jn][1],
                                bh[2*jn+1][0], bh[2*jn+1][1], oh);
                    }
                    #pragma unroll
                    for (int nt = 0; nt < 4; nt++)
                        MMA_BF16(c[nt], ah, bh[nt]);
                }
            }

            // ---- gates fully in registers (nt = gate index i,f,g,o) ----
            const int pp = (s + 1) & 1;
            #pragma unroll
            for (int half = 0; half < 2; half++) {
                int b = mrow + qrow + half * 8;
                float hh[2];
                #pragma unroll
                for (int u = 0; u < 2; u++) {
                    int e = half * 2 + u;
                    float gi = fsig(c[0][e]);
                    float gf = fsig(c[1][e]);
                    float gg = fmaxf(c[2][e], 0.f);
                    float go = fsig(c[3][e]);
                    float cv = gf * cell[half][u] + gi * gg;
                    cell[half][u] = cv;
                    hh[u] = go * fmaxf(cv, 0.f);
                }
                __nv_bfloat162 vh;
                vh.x = __float2bfloat16(hh[0]);
                vh.y = __float2bfloat16(hh[1]);
                int kk = slice * 8 + qcol;
                *(__nv_bfloat162*)&g_hb[dir][pp][0][b][kk] = vh;
                if (s == TLEN - 1) {
                    float2 vf; vf.x = hh[0]; vf.y = hh[1];
                    *(float2*)&g_h[dir][0][b][kk] = vf;
                }
            }

            if (s < TLEN - 1) {
                BAR_SYNC(1, 128);      // consumer group: h stores done
                if (tid == 0) {
                    asm volatile("red.release.gpu.global.add.u32 [%0], %1;"
                                 :: "l"(&g_bar), "r"(1u) : "memory");
                }
            }
        }
    }
}

// ---------------------------------------------------------------------------
// Kernel 3: dense + softmax
// ---------------------------------------------------------------------------
__global__ __launch_bounds__(320) void dense_kernel(
    const float* __restrict__ Wd, const float* __restrict__ bd,
    float* __restrict__ out)
{
    const int b = blockIdx.x;
    const int w = threadIdx.x >> 5, lane = threadIdx.x & 31;
    __shared__ float logits[NCLSN];

    float sum = 0.f;
    for (int k = lane; k < 2 * HIDN; k += 32) {
        float hv = (k < HIDN) ? g_h[0][0][b][k] : g_h[1][0][b][k - HIDN];
        sum = fmaf(hv, Wd[k * NCLSN + w], sum);
    }
    #pragma unroll
    for (int off = 16; off > 0; off >>= 1)
        sum += __shfl_down_sync(0xffffffffu, sum, off);
    if (lane == 0) logits[w] = sum + bd[w];
    __syncthreads();

    if (threadIdx.x == 0) {
        float mx = logits[0];
        #pragma unroll
        for (int n = 1; n < NCLSN; n++) mx = fmaxf(mx, logits[n]);
        float es[NCLSN], ssum = 0.f;
        #pragma unroll
        for (int n = 0; n < NCLSN; n++) { es[n] = expf(logits[n] - mx); ssum += es[n]; }
        float inv = 1.f / ssum;
        #pragma unroll
        for (int n = 0; n < NCLSN; n++) out[b * NCLSN + n] = es[n] * inv;
    }
}

// ---------------------------------------------------------------------------
extern "C" void kernel_launch(void* const* d_in, const int* in_sizes, int n_in,
                              void* d_out, int out_size)
{
    const int*   x    = (const int*)  d_in[0];
    const float* emb  = (const float*)d_in[1];
    const float* Wx_f = (const float*)d_in[2];
    const float* Wh_f = (const float*)d_in[3];
    const float* b_f  = (const float*)d_in[4];
    const float* Wx_b = (const float*)d_in[5];
    const float* Wh_b = (const float*)d_in[6];
    const float* b_b  = (const float*)d_in[7];
    const float* Wd   = (const float*)d_in[8];
    const float* bd   = (const float*)d_in[9];
    float* out = (float*)d_out;

    (void)in_sizes; (void)n_in; (void)out_size;

    cudaFuncSetAttribute(gemm_mma,
                         cudaFuncAttributeMaxDynamicSharedMemorySize, GT_SMEM);
    cudaFuncSetAttribute(lstm_kernel,
                         cudaFuncAttributeMaxDynamicSharedMemorySize, LSTM_SMEM_BYTES);

    prep_w<<<dim3(G4, 2), KPAD>>>(Wx_f, b_f, Wx_b, b_b);
    prep_wh<<<dim3(G4, 2), HIDN>>>(Wh_f, Wh_b);
    prep_a<<<MROWS, KPAD>>>(x, emb);
    gemm_mma<<<2 * 128 * 16, 256, GT_SMEM>>>();
    lstm_kernel<<<128, 256, LSTM_SMEM_BYTES>>>();
    dense_kernel<<<BATCHN, 320>>>(Wd, bd, out);
}

// round 17
// speedup vs baseline: 1.8145x; 1.0137x over previous
#include <cuda_runtime.h>
#include <cuda_bf16.h>
#include <math.h>
#include <stdint.h>

#define VOCABN 50000
#define EMBN   300
#define KPAD   320     // EMB padded: 5 chunks of 64
#define TLEN   256
#define HIDN   512
#define G4     2048    // 4*HID
#define NCLSN  10
#define BATCHN 64
#define MROWS  (TLEN*BATCHN)

// ---------------------------------------------------------------------------
// Device scratch
// ---------------------------------------------------------------------------
__device__ __align__(256) __nv_bfloat16 g_xz[2][TLEN][BATCHN][G4]; // bf16 now
__device__ __align__(256) float g_h[2][2][BATCHN][HIDN];   // fp32 h (final step, for dense)
__device__ unsigned g_bar;                                 // grid barrier counter

__device__ __align__(256) __nv_bfloat16 g_Ahi[(size_t)MROWS * KPAD];
__device__ __align__(256) __nv_bfloat16 g_Bhi[(size_t)2 * G4 * KPAD];
__device__ __align__(256) float g_biasp[2 * G4];

// recurrence operands: h and Wh^T as bf16 (hi plane only)
__device__ __align__(256) __nv_bfloat16 g_hb[2][2][2][BATCHN][HIDN];   // [dir][pp][plane][b][k]
__device__ __align__(256) __nv_bfloat16 g_WhT[2][2][G4][HIDN];         // [dir][plane][p][k]

__device__ __forceinline__ int perm_src(int p) {
    return ((p >> 3) & 3) * HIDN + (p >> 5) * 8 + (p & 7);
}

__device__ __forceinline__ uint32_t smem_to_u32(const void* p) {
    uint32_t a;
    asm("{ .reg .u64 t; cvta.to.shared.u64 t, %1; cvt.u32.u64 %0, t; }"
        : "=r"(a) : "l"(p));
    return a;
}

// ---------------------------------------------------------------------------
// mma.sync / ldmatrix / cp.async helpers (baseline PTX, no 'a' features)
// ---------------------------------------------------------------------------
#define LDSM_X4(r0, r1, r2, r3, addr) \
    asm volatile("ldmatrix.sync.aligned.m8n8.x4.shared.b16 {%0,%1,%2,%3}, [%4];" \
        : "=r"(r0), "=r"(r1), "=r"(r2), "=r"(r3) : "r"(addr))

#define MMA_BF16(c, a, b) \
    asm volatile("mma.sync.aligned.m16n8k16.row.col.f32.bf16.bf16.f32 " \
        "{%0,%1,%2,%3}, {%4,%5,%6,%7}, {%8,%9}, {%0,%1,%2,%3};" \
        : "+f"((c)[0]), "+f"((c)[1]), "+f"((c)[2]), "+f"((c)[3]) \
        : "r"((a)[0]), "r"((a)[1]), "r"((a)[2]), "r"((a)[3]), \
          "r"((b)[0]), "r"((b)[1]))

#define CP_ASYNC16(dst, src) \
    asm volatile("cp.async.cg.shared.global [%0], [%1], 16;" \
        :: "r"(dst), "l"(src) : "memory")
#define CP_COMMIT() asm volatile("cp.async.commit_group;" ::: "memory")
#define CP_WAIT1()  asm volatile("cp.async.wait_group 1;" ::: "memory")
#define CP_WAIT0()  asm volatile("cp.async.wait_group 0;" ::: "memory")

#define BAR_SYNC(id, n) \
    asm volatile("bar.sync %0, %1;" :: "r"(id), "r"(n) : "memory")

// swizzle of a 16B-chunk index within a 1KB/128B row (XOR low 3 bits, row&7)
__device__ __forceinline__ uint32_t swz16(uint32_t c16, uint32_t row) {
    return (c16 & ~7u) | ((c16 ^ row) & 7u);
}

__device__ __forceinline__ float fsig(float x) {
    return __fdividef(1.f, 1.f + __expf(-x));
}

// ---------------------------------------------------------------------------
// Prep kernels (bf16 round-to-nearest)
// ---------------------------------------------------------------------------
__global__ __launch_bounds__(KPAD) void prep_w(
    const float* __restrict__ Wx_f, const float* __restrict__ b_f,
    const float* __restrict__ Wx_b, const float* __restrict__ b_b)
{
    int n = blockIdx.x, dir = blockIdx.y, k = threadIdx.x;
    if (n == 0 && dir == 0 && k == 0) g_bar = 0u;     // grid-barrier reset
    int src = perm_src(n);
    const float* Wx = dir ? Wx_b : Wx_f;
    float v = (k < EMBN) ? Wx[(size_t)k * G4 + src] : 0.f;
    g_Bhi[(size_t)(dir * G4 + n) * KPAD + k] = __float2bfloat16(v);
    if (k == 0) g_biasp[dir * G4 + n] = (dir ? b_b : b_f)[src];
}

__global__ __launch_bounds__(KPAD) void prep_a(
    const int* __restrict__ x, const float* __restrict__ emb)
{
    int row = blockIdx.x;
    int t = row >> 6, b = row & 63;
    __shared__ int tok;
    if (threadIdx.x == 0) tok = x[b * TLEN + t];
    __syncthreads();
    int k = threadIdx.x;
    float v = (k < EMBN) ? emb[(size_t)tok * EMBN + k] : 0.f;
    g_Ahi[(size_t)row * KPAD + k] = __float2bfloat16(v);
}

__global__ __launch_bounds__(HIDN) void prep_wh(
    const float* __restrict__ Wh_f, const float* __restrict__ Wh_b)
{
    int p = blockIdx.x, dir = blockIdx.y, k = threadIdx.x;
    int src = perm_src(p);
    float v = (dir ? Wh_b : Wh_f)[(size_t)k * G4 + src];
    g_WhT[dir][0][p][k] = __float2bfloat16(v);
}

// ---------------------------------------------------------------------------
// Tensor-core input projection — pure bf16, k64 chunks (verified 129us).
// NEW: xz output stored as bf16 (halves the 268MB store traffic).
// ---------------------------------------------------------------------------
#define GT_STAGE 32768
#define GT_SMEM  (2 * GT_STAGE)
#define NCHUNK   5

__global__ __launch_bounds__(256, 2) void gemm_mma()
{
    extern __shared__ char sm[];
    const uint32_t smb = smem_to_u32(sm);
    const int tid = threadIdx.x, wid = tid >> 5, lane = tid & 31;

    const int ntile = blockIdx.x & 15;
    const int mtile = (blockIdx.x >> 4) & 127;
    const int dir   = blockIdx.x >> 11;
    const int m0 = mtile * 128, n0 = ntile * 128;

    const int mwarp = (wid >> 2) * 64;
    const int nwarp = (wid & 3) * 32;

    const int crow = tid >> 3;
    const int cc   = tid & 7;

    const int a_row = (lane & 7) + ((lane >> 3) & 1) * 8;
    const int a_cad = (lane >> 4) & 1;
    const int b_row = (lane & 7) + ((lane >> 4) & 1) * 8;
    const int b_cad = (lane >> 3) & 1;

    float c[4][4][4];
    #pragma unroll
    for (int i = 0; i < 4; i++)
        #pragma unroll
        for (int j = 0; j < 4; j++)
            #pragma unroll
            for (int e = 0; e < 4; e++) c[i][j][e] = 0.f;

    #define ISSUE_COPY(kc, stage) do {                                         \
        uint32_t sA = smb + (stage) * GT_STAGE;                                \
        uint32_t sB = sA + 16384;                                              \
        _Pragma("unroll")                                                      \
        for (int q = 0; q < 4; q++) {                                          \
            int row = crow + q * 32;                                           \
            uint32_t dof = (uint32_t)row * 128 + ((cc ^ (row & 7)) * 16);      \
            const __nv_bfloat16* sa = g_Ahi +                                  \
                (size_t)(m0 + row) * KPAD + (kc) * 64 + cc * 8;                \
            const __nv_bfloat16* sb = g_Bhi +                                  \
                (size_t)(dir * G4 + n0 + row) * KPAD + (kc) * 64 + cc * 8;     \
            CP_ASYNC16(sA + dof, sa);                                          \
            CP_ASYNC16(sB + dof, sb);                                          \
        }                                                                      \
        CP_COMMIT();                                                           \
    } while (0)

    ISSUE_COPY(0, 0);

    #pragma unroll 1
    for (int kc = 0; kc < NCHUNK; kc++) {
        if (kc + 1 < NCHUNK) {
            ISSUE_COPY(kc + 1, (kc + 1) & 1);
            CP_WAIT1();
        } else {
            CP_WAIT0();
        }
        __syncthreads();

        const uint32_t sA = smb + (kc & 1) * GT_STAGE;
        const uint32_t sB = sA + 16384;

        #pragma unroll
        for (int ks = 0; ks < 4; ks++) {
            uint32_t ah[4][4], bh[4][2];
            #pragma unroll
            for (int mt = 0; mt < 4; mt++) {
                int row = mwarp + mt * 16 + a_row;
                int swzr = row & 7;
                uint32_t oh = sA + (uint32_t)row * 128 +
                              (((ks * 2 + a_cad) ^ swzr) * 16);
                LDSM_X4(ah[mt][0], ah[mt][1], ah[mt][2], ah[mt][3], oh);
            }
            #pragma unroll
            for (int j = 0; j < 2; j++) {
                int row = nwarp + j * 16 + b_row;
                int swzr = row & 7;
                uint32_t oh = sB + (uint32_t)row * 128 +
                              (((ks * 2 + b_cad) ^ swzr) * 16);
                LDSM_X4(bh[2*j][0], bh[2*j][1], bh[2*j+1][0], bh[2*j+1][1], oh);
            }
            #pragma unroll
            for (int mt = 0; mt < 4; mt++)
                #pragma unroll
                for (int nt = 0; nt < 4; nt++)
                    MMA_BF16(c[mt][nt], ah[mt], bh[nt]);
        }
        __syncthreads();
    }

    const int qrow = lane >> 2;
    const int qcol = (lane & 3) * 2;
    #pragma unroll
    for (int nt = 0; nt < 4; nt++) {
        int coll = nwarp + nt * 8 + qcol;
        int col  = n0 + coll;
        float2 bv = *(const float2*)&g_biasp[dir * G4 + col];
        #pragma unroll
        for (int mt = 0; mt < 4; mt++) {
            #pragma unroll
            for (int half = 0; half < 2; half++) {
                int g = m0 + mwarp + mt * 16 + qrow + half * 8;
                int t = g >> 6, b = g & 63;
                int tout = dir ? (TLEN - 1 - t) : t;
                float2 v;
                v.x = c[mt][nt][half * 2 + 0] + bv.x;
                v.y = c[mt][nt][half * 2 + 1] + bv.y;
                *(__nv_bfloat162*)&g_xz[dir][tout][b][col] =
                    __float22bfloat162_rn(v);
            }
        }
    }
}

// ---------------------------------------------------------------------------
// Kernel 2: persistent bidirectional LSTM recurrence, warp-specialized
// (verified 926us w/ per-pair handoff). NEW: xz read as bf162 pairs.
// ---------------------------------------------------------------------------
#define LS_A     0                   // h hi plane: 64KB (rows b, 1KB each)
#define LS_B     65536               // Wh hi plane: 32KB (rows n, 1KB each)
#define LSTM_SMEM_BYTES 98304

__global__ __launch_bounds__(256, 1) void lstm_kernel()
{
    extern __shared__ char sm[];
    const uint32_t smb = smem_to_u32(sm);

    const int tid   = threadIdx.x;
    const int wid   = tid >> 5, lane = tid & 31;
    const int dir   = blockIdx.x >> 6;
    const int slice = blockIdx.x & 63;

    // ---- one-time: load Wh^T slice (hi plane) into smem (all warps) ----
    #pragma unroll
    for (int i = tid; i < 2048; i += 256) {
        int row = (i >> 6) & 31;
        int c16 = i & 63;
        const __nv_bfloat16* src = &g_WhT[dir][0][slice * 32 + row][c16 * 8];
        uint32_t dst = smb + LS_B + row * 1024 + swz16(c16, row) * 16;
        CP_ASYNC16(dst, src);
    }
    CP_COMMIT();
    CP_WAIT0();
    __syncthreads();

    const int a_row = (lane & 7) + ((lane >> 3) & 1) * 8;
    const int a_cad = (lane >> 4) & 1;
    const int b_row = (lane & 7) + ((lane >> 4) & 1) * 8;
    const int b_cad = (lane >> 3) & 1;
    const int qrow  = lane >> 2;
    const int qcol  = (lane & 3) * 2;
    const unsigned nb = gridDim.x;

    const int mrow = (wid & 3) * 16;
    const int pw   = wid - 4;

    float cell[2][2];
    cell[0][0] = cell[0][1] = cell[1][0] = cell[1][1] = 0.f;

    for (int s = 0; s < TLEN; s++) {
        // ---- producers: wait for all CTAs' h(s-1), then stage own 16 rows ----
        if (wid >= 4 && s > 0) {
            if (tid == 128) {
                unsigned target = (unsigned)s * nb;
                unsigned v;
                do {
                    asm volatile("ld.acquire.gpu.global.u32 %0, [%1];"
                                 : "=r"(v) : "l"(&g_bar) : "memory");
                } while (v < target);
            }
            BAR_SYNC(2, 128);
            const __nv_bfloat16* hb = &g_hb[dir][s & 1][0][0][0];
            #pragma unroll
            for (int q = 0; q < 32; q++) {
                int i   = lane + q * 32;
                int row = pw * 16 + (i >> 6);
                int c16 = i & 63;
                const __nv_bfloat16* src = hb + (size_t)row * HIDN + c16 * 8;
                uint32_t dst = smb + LS_A + row * 1024 + swz16(c16, row) * 16;
                CP_ASYNC16(dst, src);
            }
            CP_COMMIT();
            CP_WAIT0();
            BAR_SYNC(3 + pw, 64);      // hand off to consumer pw
        }

        if (wid < 4) {
            // prefetch xz(s) as bf16 pairs (overlaps producer staging)
            float c[4][4];
            #pragma unroll
            for (int half = 0; half < 2; half++) {
                int b = mrow + qrow + half * 8;
                const __nv_bfloat16* xzp = &g_xz[dir][s][b][slice * 32];
                #pragma unroll
                for (int nt = 0; nt < 4; nt++) {
                    __nv_bfloat162 v =
                        *(const __nv_bfloat162*)&xzp[nt * 8 + qcol];
                    c[nt][half * 2 + 0] = __bfloat162float(v.x);
                    c[nt][half * 2 + 1] = __bfloat162float(v.y);
                }
            }

            if (s > 0) {
                BAR_SYNC(3 + wid, 64);  // wait for own producer's rows
                #pragma unroll 4
                for (int j = 0; j < 32; j++) {
                    uint32_t ah[4], bh[4][2];
                    {
                        int row = mrow + a_row;
                        uint32_t oh = smb + LS_A + row * 1024 +
                                      swz16(2 * j + a_cad, row) * 16;
                        LDSM_X4(ah[0], ah[1], ah[2], ah[3], oh);
                    }
                    #pragma unroll
                    for (int jn = 0; jn < 2; jn++) {
                        int row = jn * 16 + b_row;
                        uint32_t oh = smb + LS_B + row * 1024 +
                                      swz16(2 * j + b_cad, row) * 16;
                        LDSM_X4(bh[2*jn][0], bh[2*jn][1],
                                bh[2*jn+1][0], bh[2*jn+1][1], oh);
                    }
                    #pragma unroll
                    for (int nt = 0; nt < 4; nt++)
                        MMA_BF16(c[nt], ah, bh[nt]);
                }
            }

            // ---- gates fully in registers (nt = gate index i,f,g,o) ----
            const int pp = (s + 1) & 1;
            #pragma unroll
            for (int half = 0; half < 2; half++) {
                int b = mrow + qrow + half * 8;
                float hh[2];
                #pragma unroll
                for (int u = 0; u < 2; u++) {
                    int e = half * 2 + u;
                    float gi = fsig(c[0][e]);
                    float gf = fsig(c[1][e]);
                    float gg = fmaxf(c[2][e], 0.f);
                    float go = fsig(c[3][e]);
                    float cv = gf * cell[half][u] + gi * gg;
                    cell[half][u] = cv;
                    hh[u] = go * fmaxf(cv, 0.f);
                }
                __nv_bfloat162 vh;
                vh.x = __float2bfloat16(hh[0]);
                vh.y = __float2bfloat16(hh[1]);
                int kk = slice * 8 + qcol;
                *(__nv_bfloat162*)&g_hb[dir][pp][0][b][kk] = vh;
                if (s == TLEN - 1) {
                    float2 vf; vf.x = hh[0]; vf.y = hh[1];
                    *(float2*)&g_h[dir][0][b][kk] = vf;
                }
            }

            if (s < TLEN - 1) {
                BAR_SYNC(1, 128);
                if (tid == 0) {
                    asm volatile("red.release.gpu.global.add.u32 [%0], %1;"
                                 :: "l"(&g_bar), "r"(1u) : "memory");
                }
            }
        }
    }
}

// ---------------------------------------------------------------------------
// Kernel 3: dense + softmax
// ---------------------------------------------------------------------------
__global__ __launch_bounds__(320) void dense_kernel(
    const float* __restrict__ Wd, const float* __restrict__ bd,
    float* __restrict__ out)
{
    const int b = blockIdx.x;
    const int w = threadIdx.x >> 5, lane = threadIdx.x & 31;
    __shared__ float logits[NCLSN];

    float sum = 0.f;
    for (int k = lane; k < 2 * HIDN; k += 32) {
        float hv = (k < HIDN) ? g_h[0][0][b][k] : g_h[1][0][b][k - HIDN];
        sum = fmaf(hv, Wd[k * NCLSN + w], sum);
    }
    #pragma unroll
    for (int off = 16; off > 0; off >>= 1)
        sum += __shfl_down_sync(0xffffffffu, sum, off);
    if (lane == 0) logits[w] = sum + bd[w];
    __syncthreads();

    if (threadIdx.x == 0) {
        float mx = logits[0];
        #pragma unroll
        for (int n = 1; n < NCLSN; n++) mx = fmaxf(mx, logits[n]);
        float es[NCLSN], ssum = 0.f;
        #pragma unroll
        for (int n = 0; n < NCLSN; n++) { es[n] = expf(logits[n] - mx); ssum += es[n]; }
        float inv = 1.f / ssum;
        #pragma unroll
        for (int n = 0; n < NCLSN; n++) out[b * NCLSN + n] = es[n] * inv;
    }
}

// ---------------------------------------------------------------------------
extern "C" void kernel_launch(void* const* d_in, const int* in_sizes, int n_in,
                              void* d_out, int out_size)
{
    const int*   x    = (const int*)  d_in[0];
    const float* emb  = (const float*)d_in[1];
    const float* Wx_f = (const float*)d_in[2];
    const float* Wh_f = (const float*)d_in[3];
    const float* b_f  = (const float*)d_in[4];
    const float* Wx_b = (const float*)d_in[5];
    const float* Wh_b = (const float*)d_in[6];
    const float* b_b  = (const float*)d_in[7];
    const float* Wd   = (const float*)d_in[8];
    const float* bd   = (const float*)d_in[9];
    float* out = (float*)d_out;

    (void)in_sizes; (void)n_in; (void)out_size;

    cudaFuncSetAttribute(gemm_mma,
                         cudaFuncAttributeMaxDynamicSharedMemorySize, GT_SMEM);
    cudaFuncSetAttribute(lstm_kernel,
                         cudaFuncAttributeMaxDynamicSharedMemorySize, LSTM_SMEM_BYTES);

    prep_w<<<dim3(G4, 2), KPAD>>>(Wx_f, b_f, Wx_b, b_b);
    prep_wh<<<dim3(G4, 2), HIDN>>>(Wh_f, Wh_b);
    prep_a<<<MROWS, KPAD>>>(x, emb);
    gemm_mma<<<2 * 128 * 16, 256, GT_SMEM>>>();
    lstm_kernel<<<128, 256, LSTM_SMEM_BYTES>>>();
    dense_kernel<<<BATCHN, 320>>>(Wd, bd, out);
}